// round 4
// baseline (speedup 1.0000x reference)
#include <cuda_runtime.h>
#include <math.h>

#define NMAX 100000
#define EMAX 600000
#define IN_F 128
#define OUT_F 64

// Scratch (static device globals — allocation-free per harness rules)
__device__ float g_Wsn[IN_F * OUT_F];
__device__ float g_xp[(size_t)NMAX * OUT_F];
__device__ float g_deg[NMAX];
__device__ float g_w[EMAX];
__device__ int   g_is64;   // 1 if edge_index is int64 on device, 0 if int32

__device__ __forceinline__ long long load_idx(const void* ei, size_t pos, int is64) {
    if (is64) return ((const long long*)ei)[pos];
    return (long long)(((const int*)ei)[pos]);
}

// ---------------------------------------------------------------------------
// 1) k_prep (block-switched):
//    block 0: detect edge_index dtype (int64 low words → odd u32 words all 0)
//    block 1: spectral norm -> g_Wsn
//    blocks 2..: g_deg init to 1.0 (self-loop)
// ---------------------------------------------------------------------------
__global__ void k_prep(const unsigned int* __restrict__ ei_u32, int nwords,
                       const float* __restrict__ W, const float* __restrict__ u,
                       int N) {
    int t = threadIdx.x;
    int b = blockIdx.x;

    if (b == 0) {
        // dtype detect
        __shared__ int any;
        if (t == 0) any = 0;
        __syncthreads();
        int limit = nwords < 8192 ? nwords : 8192;
        for (int i = 1 + 2 * t; i < limit; i += 2 * blockDim.x)
            if (ei_u32[i] != 0u) any = 1;
        __syncthreads();
        if (t == 0) g_is64 = (any == 0) ? 1 : 0;
        return;
    }
    if (b == 1) {
        // spectral norm (256 threads; work on t<128)
        __shared__ float su[IN_F];
        __shared__ float sv[OUT_F];
        __shared__ float red[IN_F];

        if (t < IN_F) su[t] = u[t];
        __syncthreads();

        float tj = 0.f;
        if (t < OUT_F) {
            #pragma unroll 8
            for (int i = 0; i < IN_F; i++) tj += W[i * OUT_F + t] * su[i];
        }
        if (t < IN_F) red[t] = (t < OUT_F) ? tj * tj : 0.f;
        __syncthreads();
        for (int s = 64; s > 0; s >>= 1) {
            if (t < s) red[t] += red[t + s];
            __syncthreads();
        }
        float tn = sqrtf(red[0]) + 1e-12f;
        __syncthreads();
        if (t < OUT_F) sv[t] = tj / tn;
        __syncthreads();

        float wv = 0.f;
        if (t < IN_F) {
            #pragma unroll 8
            for (int j = 0; j < OUT_F; j++) wv += W[t * OUT_F + j] * sv[j];
            red[t] = wv * wv;
        }
        __syncthreads();
        for (int s = 64; s > 0; s >>= 1) {
            if (t < s) red[t] += red[t + s];
            __syncthreads();
        }
        float s2 = red[0];
        float sigma = s2 / (sqrtf(s2) + 1e-12f);
        float inv = 1.0f / sigma;
        for (int idx = t; idx < IN_F * OUT_F; idx += blockDim.x)
            g_Wsn[idx] = W[idx] * inv;
        return;
    }
    // deg init
    int i = (b - 2) * blockDim.x + t;
    if (i < N) g_deg[i] = 1.0f;
}

// ---------------------------------------------------------------------------
// 2) k_deg: 4 edges/thread. g_w[e] = sigmoid(ew[e]); deg[col] += w.
// ---------------------------------------------------------------------------
__global__ void k_deg(const void* __restrict__ ei, const float* __restrict__ ew, int E) {
    int e = (blockIdx.x * blockDim.x + threadIdx.x) * 4;
    if (e >= E) return;
    int is64 = g_is64;

    if (e + 3 < E) {
        float4 w4 = *reinterpret_cast<const float4*>(ew + e);
        float4 s;
        s.x = 1.0f / (1.0f + expf(-w4.x));
        s.y = 1.0f / (1.0f + expf(-w4.y));
        s.z = 1.0f / (1.0f + expf(-w4.z));
        s.w = 1.0f / (1.0f + expf(-w4.w));
        *reinterpret_cast<float4*>(g_w + e) = s;
        int c0, c1, c2, c3;
        if (is64) {
            const longlong2* p = reinterpret_cast<const longlong2*>((const long long*)ei + E + e);
            longlong2 a = p[0], bq = p[1];
            c0 = (int)a.x; c1 = (int)a.y; c2 = (int)bq.x; c3 = (int)bq.y;
        } else {
            int4 cc = *reinterpret_cast<const int4*>((const int*)ei + E + e);
            c0 = cc.x; c1 = cc.y; c2 = cc.z; c3 = cc.w;
        }
        atomicAdd(&g_deg[c0], s.x);
        atomicAdd(&g_deg[c1], s.y);
        atomicAdd(&g_deg[c2], s.z);
        atomicAdd(&g_deg[c3], s.w);
    } else {
        for (int k = e; k < E; k++) {
            float w = 1.0f / (1.0f + expf(-ew[k]));
            g_w[k] = w;
            long long c = load_idx(ei, (size_t)E + k, is64);
            atomicAdd(&g_deg[c], w);
        }
    }
}

// ---------------------------------------------------------------------------
// 3) GEMM: xp = x @ W_sn ; out = xp/deg + bias ; stash xp.
//    128 rows/block, 1 row/thread, packed fma.rn.f32x2 accumulators.
// ---------------------------------------------------------------------------
#define BK 32
__global__ void __launch_bounds__(128) k_gemm(const float* __restrict__ x,
                                              const float* __restrict__ bias,
                                              float* __restrict__ out, int N) {
    __shared__ float      xs[128][BK + 1];
    __shared__ ulonglong2 ws[BK * 16];  // W chunk: [BK][64 floats] = [BK][16 u64x2]

    int t = threadIdx.x;
    int row0 = blockIdx.x * 128;
    int row = row0 + t;

    unsigned long long acc[32];
    #pragma unroll
    for (int j = 0; j < 32; j++) acc[j] = 0ull;

    const ulonglong2* Wg = reinterpret_cast<const ulonglong2*>(g_Wsn);

    for (int kc = 0; kc < IN_F; kc += BK) {
        // W chunk: BK*16 ulonglong2 = 512 entries; 4/thread
        #pragma unroll
        for (int i = 0; i < 4; i++) {
            int idx = t + i * 128;
            ws[idx] = Wg[kc * 16 + idx];
        }
        // x tile: 128 rows x BK floats, float4 global loads, scalar smem stores
        #pragma unroll
        for (int i = 0; i < 8; i++) {
            int idx = t + i * 128;                // 0..1023 float4 slots
            int r = idx / (BK / 4);
            int kq = (idx % (BK / 4)) * 4;
            float4 v = make_float4(0.f, 0.f, 0.f, 0.f);
            if (row0 + r < N)
                v = *reinterpret_cast<const float4*>(&x[(size_t)(row0 + r) * IN_F + kc + kq]);
            xs[r][kq + 0] = v.x;
            xs[r][kq + 1] = v.y;
            xs[r][kq + 2] = v.z;
            xs[r][kq + 3] = v.w;
        }
        __syncthreads();

        #pragma unroll 4
        for (int kk = 0; kk < BK; kk++) {
            float xv = xs[t][kk];
            unsigned long long xv2;
            asm("mov.b64 %0, {%1, %1};" : "=l"(xv2) : "f"(xv));
            const ulonglong2* wrow = &ws[kk * 16];
            #pragma unroll
            for (int j = 0; j < 16; j++) {
                ulonglong2 w2 = wrow[j];
                asm("fma.rn.f32x2 %0, %1, %2, %0;" : "+l"(acc[2 * j])     : "l"(xv2), "l"(w2.x));
                asm("fma.rn.f32x2 %0, %1, %2, %0;" : "+l"(acc[2 * j + 1]) : "l"(xv2), "l"(w2.y));
            }
        }
        __syncthreads();
    }

    if (row < N) {
        float invd = 1.0f / g_deg[row];
        float4* xpp = reinterpret_cast<float4*>(&g_xp[(size_t)row * OUT_F]);
        float4* op  = reinterpret_cast<float4*>(&out[(size_t)row * OUT_F]);
        const float4* b4 = reinterpret_cast<const float4*>(bias);
        #pragma unroll
        for (int j = 0; j < 16; j++) {
            float f0, f1, f2, f3;
            asm("mov.b64 {%0, %1}, %2;" : "=f"(f0), "=f"(f1) : "l"(acc[2 * j]));
            asm("mov.b64 {%0, %1}, %2;" : "=f"(f2), "=f"(f3) : "l"(acc[2 * j + 1]));
            xpp[j] = make_float4(f0, f1, f2, f3);
            float4 bb = b4[j];
            op[j] = make_float4(fmaf(f0, invd, bb.x), fmaf(f1, invd, bb.y),
                                fmaf(f2, invd, bb.z), fmaf(f3, invd, bb.w));
        }
    }
}

// ---------------------------------------------------------------------------
// 4) Scatter: out[col] += xp[row] * (dis[row]*w*dis[col]).
//    16 lanes/edge; lane 0 computes coef + indices, shfl-broadcast to group.
// ---------------------------------------------------------------------------
__global__ void k_scatter(const void* __restrict__ ei, float* __restrict__ out, int E) {
    int gid = blockIdx.x * blockDim.x + threadIdx.x;
    int e = gid >> 4;
    bool valid = (e < E);
    int ec = valid ? e : (E - 1);
    int lane = gid & 15;
    int wl = threadIdx.x & 31;
    int is64 = g_is64;

    int r = 0, c = 0;
    float ne = 0.f;
    if (lane == 0) {
        r = (int)load_idx(ei, (size_t)ec, is64);
        c = (int)load_idx(ei, (size_t)E + ec, is64);
        ne = g_w[ec] * rsqrtf(g_deg[r]) * rsqrtf(g_deg[c]);
    }
    int src = wl & 16;  // lane 0 or 16 of the warp
    r  = __shfl_sync(0xffffffffu, r, src);
    c  = __shfl_sync(0xffffffffu, c, src);
    ne = __shfl_sync(0xffffffffu, ne, src);
    if (!valid) return;

    float4 v = *reinterpret_cast<const float4*>(&g_xp[(size_t)r * OUT_F + lane * 4]);
    float* dst = &out[(size_t)c * OUT_F + lane * 4];
    asm volatile("red.global.add.v4.f32 [%0], {%1, %2, %3, %4};"
                 :: "l"(dst), "f"(v.x * ne), "f"(v.y * ne), "f"(v.z * ne), "f"(v.w * ne)
                 : "memory");
}

// ---------------------------------------------------------------------------
// Launch
// ---------------------------------------------------------------------------
extern "C" void kernel_launch(void* const* d_in, const int* in_sizes, int n_in,
                              void* d_out, int out_size) {
    const float* x    = (const float*)d_in[0];
    const void*  ei   = d_in[1];
    const float* W    = (const float*)d_in[2];
    const float* bias = (const float*)d_in[3];
    const float* ew   = (const float*)d_in[4];
    const float* u    = (const float*)d_in[5];
    float*       out  = (float*)d_out;

    int N = in_sizes[0] / IN_F;
    int E = in_sizes[4];
    if (N > NMAX) N = NMAX;
    if (E > EMAX) E = EMAX;

    int initBlocks = (N + 255) / 256;
    k_prep<<<initBlocks + 2, 256>>>((const unsigned int*)ei, 2 * E, W, u, N);
    k_deg<<<((E + 3) / 4 + 255) / 256, 256>>>(ei, ew, E);
    k_gemm<<<(N + 127) / 128, 128>>>(x, bias, out, N);
    k_scatter<<<((E * 16) + 255) / 256, 256>>>(ei, out, E);
}

// round 5
// speedup vs baseline: 1.2976x; 1.2976x over previous
#include <cuda_runtime.h>
#include <math.h>

#define NMAX 100000
#define EMAX 600000
#define IN_F 128
#define OUT_F 64

// Scratch (static device globals — allocation-free per harness rules)
__device__ float g_Wsn[IN_F * OUT_F];
__device__ float g_xp[(size_t)NMAX * OUT_F];
__device__ float g_deg[NMAX];
__device__ float g_w[EMAX];
__device__ float g_coef[EMAX];
__device__ int2  g_rc[EMAX];
__device__ int   g_is64;   // 1 if edge_index is int64 on device, 0 if int32

__device__ __forceinline__ long long load_idx(const void* ei, size_t pos, int is64) {
    if (is64) return ((const long long*)ei)[pos];
    return (long long)(((const int*)ei)[pos]);
}

// ---------------------------------------------------------------------------
// 1) k_prep (block-switched):
//    block 0: detect edge_index dtype (int64 idx < 2^31 → odd u32 words all 0)
//    block 1: spectral norm -> g_Wsn
//    blocks 2..: g_deg init to 1.0 (self-loop)
// ---------------------------------------------------------------------------
__global__ void k_prep(const unsigned int* __restrict__ ei_u32, int nwords,
                       const float* __restrict__ W, const float* __restrict__ u,
                       int N) {
    int t = threadIdx.x;
    int b = blockIdx.x;

    if (b == 0) {
        __shared__ int any;
        if (t == 0) any = 0;
        __syncthreads();
        int limit = nwords < 8192 ? nwords : 8192;
        for (int i = 1 + 2 * t; i < limit; i += 2 * blockDim.x)
            if (ei_u32[i] != 0u) any = 1;
        __syncthreads();
        if (t == 0) g_is64 = (any == 0) ? 1 : 0;
        return;
    }
    if (b == 1) {
        __shared__ float su[IN_F];
        __shared__ float sv[OUT_F];
        __shared__ float red[IN_F];

        if (t < IN_F) su[t] = u[t];
        __syncthreads();

        float tj = 0.f;
        if (t < OUT_F) {
            #pragma unroll 8
            for (int i = 0; i < IN_F; i++) tj += W[i * OUT_F + t] * su[i];
        }
        if (t < IN_F) red[t] = (t < OUT_F) ? tj * tj : 0.f;
        __syncthreads();
        for (int s = 64; s > 0; s >>= 1) {
            if (t < s) red[t] += red[t + s];
            __syncthreads();
        }
        float tn = sqrtf(red[0]) + 1e-12f;
        __syncthreads();
        if (t < OUT_F) sv[t] = tj / tn;
        __syncthreads();

        float wv = 0.f;
        if (t < IN_F) {
            #pragma unroll 8
            for (int j = 0; j < OUT_F; j++) wv += W[t * OUT_F + j] * sv[j];
            red[t] = wv * wv;
        }
        __syncthreads();
        for (int s = 64; s > 0; s >>= 1) {
            if (t < s) red[t] += red[t + s];
            __syncthreads();
        }
        float s2 = red[0];
        float sigma = s2 / (sqrtf(s2) + 1e-12f);
        float inv = 1.0f / sigma;
        for (int idx = t; idx < IN_F * OUT_F; idx += blockDim.x)
            g_Wsn[idx] = W[idx] * inv;
        return;
    }
    int i = (b - 2) * blockDim.x + t;
    if (i < N) g_deg[i] = 1.0f;
}

// ---------------------------------------------------------------------------
// 2) k_deg: 4 edges/thread. g_w[e] = sigmoid(ew[e]); deg[col] += w.
// ---------------------------------------------------------------------------
__global__ void k_deg(const void* __restrict__ ei, const float* __restrict__ ew, int E) {
    int e = (blockIdx.x * blockDim.x + threadIdx.x) * 4;
    if (e >= E) return;
    int is64 = g_is64;

    if (e + 3 < E) {
        float4 w4 = *reinterpret_cast<const float4*>(ew + e);
        float4 s;
        s.x = 1.0f / (1.0f + expf(-w4.x));
        s.y = 1.0f / (1.0f + expf(-w4.y));
        s.z = 1.0f / (1.0f + expf(-w4.z));
        s.w = 1.0f / (1.0f + expf(-w4.w));
        *reinterpret_cast<float4*>(g_w + e) = s;
        int c0, c1, c2, c3;
        if (is64) {
            const longlong2* p = reinterpret_cast<const longlong2*>((const long long*)ei + E + e);
            longlong2 a = p[0], bq = p[1];
            c0 = (int)a.x; c1 = (int)a.y; c2 = (int)bq.x; c3 = (int)bq.y;
        } else {
            int4 cc = *reinterpret_cast<const int4*>((const int*)ei + E + e);
            c0 = cc.x; c1 = cc.y; c2 = cc.z; c3 = cc.w;
        }
        atomicAdd(&g_deg[c0], s.x);
        atomicAdd(&g_deg[c1], s.y);
        atomicAdd(&g_deg[c2], s.z);
        atomicAdd(&g_deg[c3], s.w);
    } else {
        for (int k = e; k < E; k++) {
            float w = 1.0f / (1.0f + expf(-ew[k]));
            g_w[k] = w;
            long long c = load_idx(ei, (size_t)E + k, is64);
            atomicAdd(&g_deg[c], w);
        }
    }
}

// ---------------------------------------------------------------------------
// 3) GEMM (R3 form): xp = x @ W_sn ; out = xp/deg + bias ; stash xp.
//    128 rows/block, 1 row/thread, float4 FFMA accumulators.
// ---------------------------------------------------------------------------
#define BK 32
__global__ void __launch_bounds__(128) k_gemm(const float* __restrict__ x,
                                              const float* __restrict__ bias,
                                              float* __restrict__ out, int N) {
    __shared__ float  xs[128][BK + 1];
    __shared__ float4 ws[BK * 16];  // W chunk: [BK][64] as float4

    int t = threadIdx.x;
    int row0 = blockIdx.x * 128;
    int row = row0 + t;

    float4 acc[16];
    #pragma unroll
    for (int j = 0; j < 16; j++) acc[j] = make_float4(0.f, 0.f, 0.f, 0.f);

    for (int kc = 0; kc < IN_F; kc += BK) {
        #pragma unroll
        for (int i = 0; i < 4; i++) {
            int idx = t + i * 128;
            ws[idx] = reinterpret_cast<const float4*>(g_Wsn)[kc * 16 + idx];
        }
        #pragma unroll
        for (int i = 0; i < 32; i++) {
            int idx = t + i * 128;
            int r = idx / BK;
            int kk = idx % BK;
            float v = (row0 + r < N) ? x[(size_t)(row0 + r) * IN_F + kc + kk] : 0.f;
            xs[r][kk] = v;
        }
        __syncthreads();
        #pragma unroll 4
        for (int kk = 0; kk < BK; kk++) {
            float xv = xs[t][kk];
            #pragma unroll
            for (int j = 0; j < 16; j++) {
                float4 w = ws[kk * 16 + j];
                acc[j].x += xv * w.x;
                acc[j].y += xv * w.y;
                acc[j].z += xv * w.z;
                acc[j].w += xv * w.w;
            }
        }
        __syncthreads();
    }

    if (row < N) {
        float invd = 1.0f / g_deg[row];
        float4* xpp = reinterpret_cast<float4*>(&g_xp[(size_t)row * OUT_F]);
        float4* op = reinterpret_cast<float4*>(&out[(size_t)row * OUT_F]);
        const float4* b4 = reinterpret_cast<const float4*>(bias);
        #pragma unroll
        for (int j = 0; j < 16; j++) {
            xpp[j] = acc[j];
            float4 bb = b4[j];
            float4 o;
            o.x = acc[j].x * invd + bb.x;
            o.y = acc[j].y * invd + bb.y;
            o.z = acc[j].z * invd + bb.z;
            o.w = acc[j].w * invd + bb.w;
            op[j] = o;
        }
    }
}

// ---------------------------------------------------------------------------
// 4) k_coef: coef = rsqrt(deg[r]) * w * rsqrt(deg[c]); pack rc for scatter.
// ---------------------------------------------------------------------------
__global__ void k_coef(const void* __restrict__ ei, int E) {
    int e = blockIdx.x * blockDim.x + threadIdx.x;
    if (e >= E) return;
    int is64 = g_is64;
    int r = (int)load_idx(ei, (size_t)e, is64);
    int c = (int)load_idx(ei, (size_t)E + e, is64);
    g_rc[e] = make_int2(r, c);
    g_coef[e] = rsqrtf(g_deg[r]) * g_w[e] * rsqrtf(g_deg[c]);
}

// ---------------------------------------------------------------------------
// 5) Scatter: out[col] += xp[row] * coef.
//    4 lanes/edge; each lane: 4x LDG.128 (MLP) + 4x RED.128.
// ---------------------------------------------------------------------------
__global__ void k_scatter(float* __restrict__ out, int E) {
    int gid = blockIdx.x * blockDim.x + threadIdx.x;
    int e = gid >> 2;
    if (e >= E) return;
    int q = gid & 3;

    int2 rc = g_rc[e];           // broadcast across the 4-lane group
    float ne = g_coef[e];

    const float4* src = reinterpret_cast<const float4*>(&g_xp[(size_t)rc.x * OUT_F]) + q * 4;
    float*        dst = &out[(size_t)rc.y * OUT_F + q * 16];

    float4 v0 = src[0];
    float4 v1 = src[1];
    float4 v2 = src[2];
    float4 v3 = src[3];

    asm volatile("red.global.add.v4.f32 [%0], {%1, %2, %3, %4};"
                 :: "l"(dst + 0), "f"(v0.x * ne), "f"(v0.y * ne), "f"(v0.z * ne), "f"(v0.w * ne) : "memory");
    asm volatile("red.global.add.v4.f32 [%0], {%1, %2, %3, %4};"
                 :: "l"(dst + 4), "f"(v1.x * ne), "f"(v1.y * ne), "f"(v1.z * ne), "f"(v1.w * ne) : "memory");
    asm volatile("red.global.add.v4.f32 [%0], {%1, %2, %3, %4};"
                 :: "l"(dst + 8), "f"(v2.x * ne), "f"(v2.y * ne), "f"(v2.z * ne), "f"(v2.w * ne) : "memory");
    asm volatile("red.global.add.v4.f32 [%0], {%1, %2, %3, %4};"
                 :: "l"(dst + 12), "f"(v3.x * ne), "f"(v3.y * ne), "f"(v3.z * ne), "f"(v3.w * ne) : "memory");
}

// ---------------------------------------------------------------------------
// Launch
// ---------------------------------------------------------------------------
extern "C" void kernel_launch(void* const* d_in, const int* in_sizes, int n_in,
                              void* d_out, int out_size) {
    const float* x    = (const float*)d_in[0];
    const void*  ei   = d_in[1];
    const float* W    = (const float*)d_in[2];
    const float* bias = (const float*)d_in[3];
    const float* ew   = (const float*)d_in[4];
    const float* u    = (const float*)d_in[5];
    float*       out  = (float*)d_out;

    int N = in_sizes[0] / IN_F;
    int E = in_sizes[4];
    if (N > NMAX) N = NMAX;
    if (E > EMAX) E = EMAX;

    int initBlocks = (N + 255) / 256;
    k_prep<<<initBlocks + 2, 256>>>((const unsigned int*)ei, 2 * E, W, u, N);
    k_deg<<<((E + 3) / 4 + 255) / 256, 256>>>(ei, ew, E);
    k_gemm<<<(N + 127) / 128, 128>>>(x, bias, out, N);
    k_coef<<<(E + 255) / 256, 256>>>(ei, E);
    k_scatter<<<((E * 4) + 255) / 256, 256>>>(out, E);
}

// round 6
// speedup vs baseline: 1.3428x; 1.0348x over previous
#include <cuda_runtime.h>
#include <math.h>

#define NMAX 100000
#define EMAX 600000
#define IN_F 128
#define OUT_F 64

// Scratch (static device globals — allocation-free per harness rules)
__device__ float g_Wsn[IN_F * OUT_F];
__device__ float g_xp[(size_t)NMAX * OUT_F];
__device__ float g_deg[NMAX];
__device__ float g_dis[NMAX];
__device__ float g_w[EMAX];
__device__ int2  g_rc[EMAX];
__device__ int   g_is64;   // 1 if edge_index is int64 on device, 0 if int32

__device__ __forceinline__ long long load_idx(const void* ei, size_t pos, int is64) {
    if (is64) return ((const long long*)ei)[pos];
    return (long long)(((const int*)ei)[pos]);
}

// ---------------------------------------------------------------------------
// 1) k_prep (block-switched):
//    block 0: detect edge_index dtype (int64 idx < 2^31 → odd u32 words all 0)
//    block 1: spectral norm -> g_Wsn
//    blocks 2..: g_deg init to 1.0 (self-loop)
// ---------------------------------------------------------------------------
__global__ void k_prep(const unsigned int* __restrict__ ei_u32, int nwords,
                       const float* __restrict__ W, const float* __restrict__ u,
                       int N) {
    int t = threadIdx.x;
    int b = blockIdx.x;

    if (b == 0) {
        __shared__ int any;
        if (t == 0) any = 0;
        __syncthreads();
        int limit = nwords < 8192 ? nwords : 8192;
        for (int i = 1 + 2 * t; i < limit; i += 2 * blockDim.x)
            if (ei_u32[i] != 0u) any = 1;
        __syncthreads();
        if (t == 0) g_is64 = (any == 0) ? 1 : 0;
        return;
    }
    if (b == 1) {
        __shared__ float su[IN_F];
        __shared__ float sv[OUT_F];
        __shared__ float red[IN_F];

        if (t < IN_F) su[t] = u[t];
        __syncthreads();

        float tj = 0.f;
        if (t < OUT_F) {
            #pragma unroll 8
            for (int i = 0; i < IN_F; i++) tj += W[i * OUT_F + t] * su[i];
        }
        if (t < IN_F) red[t] = (t < OUT_F) ? tj * tj : 0.f;
        __syncthreads();
        for (int s = 64; s > 0; s >>= 1) {
            if (t < s) red[t] += red[t + s];
            __syncthreads();
        }
        float tn = sqrtf(red[0]) + 1e-12f;
        __syncthreads();
        if (t < OUT_F) sv[t] = tj / tn;
        __syncthreads();

        float wv = 0.f;
        if (t < IN_F) {
            #pragma unroll 8
            for (int j = 0; j < OUT_F; j++) wv += W[t * OUT_F + j] * sv[j];
            red[t] = wv * wv;
        }
        __syncthreads();
        for (int s = 64; s > 0; s >>= 1) {
            if (t < s) red[t] += red[t + s];
            __syncthreads();
        }
        float s2 = red[0];
        float sigma = s2 / (sqrtf(s2) + 1e-12f);
        float inv = 1.0f / sigma;
        for (int idx = t; idx < IN_F * OUT_F; idx += blockDim.x)
            g_Wsn[idx] = W[idx] * inv;
        return;
    }
    int i = (b - 2) * blockDim.x + t;
    if (i < N) g_deg[i] = 1.0f;
}

// ---------------------------------------------------------------------------
// 2) k_deg: 4 edges/thread. g_w[e]=sigmoid(ew[e]); deg[col]+=w; pack g_rc.
// ---------------------------------------------------------------------------
__global__ void k_deg(const void* __restrict__ ei, const float* __restrict__ ew, int E) {
    int e = (blockIdx.x * blockDim.x + threadIdx.x) * 4;
    if (e >= E) return;
    int is64 = g_is64;

    if (e + 3 < E) {
        float4 w4 = *reinterpret_cast<const float4*>(ew + e);
        float4 s;
        s.x = 1.0f / (1.0f + expf(-w4.x));
        s.y = 1.0f / (1.0f + expf(-w4.y));
        s.z = 1.0f / (1.0f + expf(-w4.z));
        s.w = 1.0f / (1.0f + expf(-w4.w));
        *reinterpret_cast<float4*>(g_w + e) = s;
        int r0, r1, r2, r3, c0, c1, c2, c3;
        if (is64) {
            const longlong2* pr = reinterpret_cast<const longlong2*>((const long long*)ei + e);
            longlong2 a = pr[0], bq = pr[1];
            r0 = (int)a.x; r1 = (int)a.y; r2 = (int)bq.x; r3 = (int)bq.y;
            const longlong2* pc = reinterpret_cast<const longlong2*>((const long long*)ei + E + e);
            longlong2 d = pc[0], f = pc[1];
            c0 = (int)d.x; c1 = (int)d.y; c2 = (int)f.x; c3 = (int)f.y;
        } else {
            int4 rr = *reinterpret_cast<const int4*>((const int*)ei + e);
            r0 = rr.x; r1 = rr.y; r2 = rr.z; r3 = rr.w;
            int4 cc = *reinterpret_cast<const int4*>((const int*)ei + E + e);
            c0 = cc.x; c1 = cc.y; c2 = cc.z; c3 = cc.w;
        }
        int4* rcp = reinterpret_cast<int4*>(&g_rc[e]);
        rcp[0] = make_int4(r0, c0, r1, c1);
        rcp[1] = make_int4(r2, c2, r3, c3);
        atomicAdd(&g_deg[c0], s.x);
        atomicAdd(&g_deg[c1], s.y);
        atomicAdd(&g_deg[c2], s.z);
        atomicAdd(&g_deg[c3], s.w);
    } else {
        for (int k = e; k < E; k++) {
            float w = 1.0f / (1.0f + expf(-ew[k]));
            g_w[k] = w;
            int r = (int)load_idx(ei, (size_t)k, is64);
            int c = (int)load_idx(ei, (size_t)E + k, is64);
            g_rc[k] = make_int2(r, c);
            atomicAdd(&g_deg[c], w);
        }
    }
}

// ---------------------------------------------------------------------------
// 3) GEMM (R3 form): xp = x @ W_sn ; out = xp/deg + bias ; stash xp, dis.
//    128 rows/block, 1 row/thread, float4 FFMA accumulators.
// ---------------------------------------------------------------------------
#define BK 32
__global__ void __launch_bounds__(128) k_gemm(const float* __restrict__ x,
                                              const float* __restrict__ bias,
                                              float* __restrict__ out, int N) {
    __shared__ float  xs[128][BK + 1];
    __shared__ float4 ws[BK * 16];  // W chunk: [BK][64] as float4

    int t = threadIdx.x;
    int row0 = blockIdx.x * 128;
    int row = row0 + t;

    float4 acc[16];
    #pragma unroll
    for (int j = 0; j < 16; j++) acc[j] = make_float4(0.f, 0.f, 0.f, 0.f);

    for (int kc = 0; kc < IN_F; kc += BK) {
        #pragma unroll
        for (int i = 0; i < 4; i++) {
            int idx = t + i * 128;
            ws[idx] = reinterpret_cast<const float4*>(g_Wsn)[kc * 16 + idx];
        }
        #pragma unroll
        for (int i = 0; i < 32; i++) {
            int idx = t + i * 128;
            int r = idx / BK;
            int kk = idx % BK;
            float v = (row0 + r < N) ? x[(size_t)(row0 + r) * IN_F + kc + kk] : 0.f;
            xs[r][kk] = v;
        }
        __syncthreads();
        #pragma unroll 4
        for (int kk = 0; kk < BK; kk++) {
            float xv = xs[t][kk];
            #pragma unroll
            for (int j = 0; j < 16; j++) {
                float4 w = ws[kk * 16 + j];
                acc[j].x += xv * w.x;
                acc[j].y += xv * w.y;
                acc[j].z += xv * w.z;
                acc[j].w += xv * w.w;
            }
        }
        __syncthreads();
    }

    if (row < N) {
        float d = g_deg[row];
        float dis = rsqrtf(d);
        float invd = 1.0f / d;
        g_dis[row] = dis;
        float4* xpp = reinterpret_cast<float4*>(&g_xp[(size_t)row * OUT_F]);
        float4* op = reinterpret_cast<float4*>(&out[(size_t)row * OUT_F]);
        const float4* b4 = reinterpret_cast<const float4*>(bias);
        #pragma unroll
        for (int j = 0; j < 16; j++) {
            xpp[j] = acc[j];
            float4 bb = b4[j];
            float4 o;
            o.x = acc[j].x * invd + bb.x;
            o.y = acc[j].y * invd + bb.y;
            o.z = acc[j].z * invd + bb.z;
            o.w = acc[j].w * invd + bb.w;
            op[j] = o;
        }
    }
}

// ---------------------------------------------------------------------------
// 4) Scatter: out[col] += xp[row] * (dis[row]*w*dis[col]).
//    4 lanes/edge; quad-broadcast loads; 4x LDG.128 + 4x RED.128 per thread.
// ---------------------------------------------------------------------------
__global__ void k_scatter(float* __restrict__ out, int E) {
    int gid = blockIdx.x * blockDim.x + threadIdx.x;
    int e = gid >> 2;
    if (e >= E) return;
    int q = gid & 3;

    int2 rc = g_rc[e];                    // broadcast within quad
    float ne = g_w[e] * g_dis[rc.x] * g_dis[rc.y];

    const float4* src = reinterpret_cast<const float4*>(&g_xp[(size_t)rc.x * OUT_F]) + q * 4;
    float*        dst = &out[(size_t)rc.y * OUT_F + q * 16];

    float4 v0 = src[0];
    float4 v1 = src[1];
    float4 v2 = src[2];
    float4 v3 = src[3];

    asm volatile("red.global.add.v4.f32 [%0], {%1, %2, %3, %4};"
                 :: "l"(dst + 0), "f"(v0.x * ne), "f"(v0.y * ne), "f"(v0.z * ne), "f"(v0.w * ne) : "memory");
    asm volatile("red.global.add.v4.f32 [%0], {%1, %2, %3, %4};"
                 :: "l"(dst + 4), "f"(v1.x * ne), "f"(v1.y * ne), "f"(v1.z * ne), "f"(v1.w * ne) : "memory");
    asm volatile("red.global.add.v4.f32 [%0], {%1, %2, %3, %4};"
                 :: "l"(dst + 8), "f"(v2.x * ne), "f"(v2.y * ne), "f"(v2.z * ne), "f"(v2.w * ne) : "memory");
    asm volatile("red.global.add.v4.f32 [%0], {%1, %2, %3, %4};"
                 :: "l"(dst + 12), "f"(v3.x * ne), "f"(v3.y * ne), "f"(v3.z * ne), "f"(v3.w * ne) : "memory");
}

// ---------------------------------------------------------------------------
// Launch (4 launches; ncu captures #4 = k_scatter)
// ---------------------------------------------------------------------------
extern "C" void kernel_launch(void* const* d_in, const int* in_sizes, int n_in,
                              void* d_out, int out_size) {
    const float* x    = (const float*)d_in[0];
    const void*  ei   = d_in[1];
    const float* W    = (const float*)d_in[2];
    const float* bias = (const float*)d_in[3];
    const float* ew   = (const float*)d_in[4];
    const float* u    = (const float*)d_in[5];
    float*       out  = (float*)d_out;

    int N = in_sizes[0] / IN_F;
    int E = in_sizes[4];
    if (N > NMAX) N = NMAX;
    if (E > EMAX) E = EMAX;

    int initBlocks = (N + 255) / 256;
    k_prep<<<initBlocks + 2, 256>>>((const unsigned int*)ei, 2 * E, W, u, N);
    k_deg<<<((E + 3) / 4 + 255) / 256, 256>>>(ei, ew, E);
    k_gemm<<<(N + 127) / 128, 128>>>(x, bias, out, N);
    k_scatter<<<((E * 4) + 255) / 256, 256>>>(out, E);
}

// round 7
// speedup vs baseline: 1.4034x; 1.0451x over previous
#include <cuda_runtime.h>
#include <math.h>

#define NMAX 100000
#define EMAX 600000
#define IN_F 128
#define OUT_F 64

// Scratch (static device globals — allocation-free per harness rules)
__device__ float g_Wsn[IN_F * OUT_F];
__device__ float g_xp[(size_t)NMAX * OUT_F];
__device__ float g_deg[NMAX];
__device__ float g_dis[NMAX];
__device__ float g_w[EMAX];
__device__ int2  g_rc[EMAX];
__device__ int   g_is64;   // 1 if edge_index is int64 on device, 0 if int32

__device__ __forceinline__ long long load_idx(const void* ei, size_t pos, int is64) {
    if (is64) return ((const long long*)ei)[pos];
    return (long long)(((const int*)ei)[pos]);
}

// ---------------------------------------------------------------------------
// 1) k_prep0: block 0 = dtype detect; block 1 = spectral norm -> g_Wsn
// ---------------------------------------------------------------------------
__global__ void k_prep0(const unsigned int* __restrict__ ei_u32, int nwords,
                        const float* __restrict__ W, const float* __restrict__ u) {
    int t = threadIdx.x;
    if (blockIdx.x == 0) {
        __shared__ int any;
        if (t == 0) any = 0;
        __syncthreads();
        int limit = nwords < 8192 ? nwords : 8192;
        for (int i = 1 + 2 * t; i < limit; i += 2 * blockDim.x)
            if (ei_u32[i] != 0u) any = 1;
        __syncthreads();
        if (t == 0) g_is64 = (any == 0) ? 1 : 0;
        return;
    }
    // spectral norm (256 threads; work on t<128)
    __shared__ float su[IN_F];
    __shared__ float sv[OUT_F];
    __shared__ float red[IN_F];

    if (t < IN_F) su[t] = u[t];
    __syncthreads();

    float tj = 0.f;
    if (t < OUT_F) {
        #pragma unroll 8
        for (int i = 0; i < IN_F; i++) tj += W[i * OUT_F + t] * su[i];
    }
    if (t < IN_F) red[t] = (t < OUT_F) ? tj * tj : 0.f;
    __syncthreads();
    for (int s = 64; s > 0; s >>= 1) {
        if (t < s) red[t] += red[t + s];
        __syncthreads();
    }
    float tn = sqrtf(red[0]) + 1e-12f;
    __syncthreads();
    if (t < OUT_F) sv[t] = tj / tn;
    __syncthreads();

    float wv = 0.f;
    if (t < IN_F) {
        #pragma unroll 8
        for (int j = 0; j < OUT_F; j++) wv += W[t * OUT_F + j] * sv[j];
        red[t] = wv * wv;
    }
    __syncthreads();
    for (int s = 64; s > 0; s >>= 1) {
        if (t < s) red[t] += red[t + s];
        __syncthreads();
    }
    float s2 = red[0];
    float sigma = s2 / (sqrtf(s2) + 1e-12f);
    float inv = 1.0f / sigma;
    for (int idx = t; idx < IN_F * OUT_F; idx += blockDim.x)
        g_Wsn[idx] = W[idx] * inv;
}

// ---------------------------------------------------------------------------
// 2) k_deginit: deg = 1.0 (self-loop)
// ---------------------------------------------------------------------------
__global__ void k_deginit(int N) {
    int i = blockIdx.x * blockDim.x + threadIdx.x;
    if (i < N) g_deg[i] = 1.0f;
}

// ---------------------------------------------------------------------------
// 3) k_deg: 4 edges/thread. g_w[e]=sigmoid(ew[e]); deg[col]+=w; pack g_rc.
// ---------------------------------------------------------------------------
__global__ void k_deg(const void* __restrict__ ei, const float* __restrict__ ew, int E) {
    int e = (blockIdx.x * blockDim.x + threadIdx.x) * 4;
    if (e >= E) return;
    int is64 = g_is64;

    if (e + 3 < E) {
        float4 w4 = *reinterpret_cast<const float4*>(ew + e);
        float4 s;
        s.x = 1.0f / (1.0f + expf(-w4.x));
        s.y = 1.0f / (1.0f + expf(-w4.y));
        s.z = 1.0f / (1.0f + expf(-w4.z));
        s.w = 1.0f / (1.0f + expf(-w4.w));
        *reinterpret_cast<float4*>(g_w + e) = s;
        int r0, r1, r2, r3, c0, c1, c2, c3;
        if (is64) {
            const longlong2* pr = reinterpret_cast<const longlong2*>((const long long*)ei + e);
            longlong2 a = pr[0], bq = pr[1];
            r0 = (int)a.x; r1 = (int)a.y; r2 = (int)bq.x; r3 = (int)bq.y;
            const longlong2* pc = reinterpret_cast<const longlong2*>((const long long*)ei + E + e);
            longlong2 d = pc[0], f = pc[1];
            c0 = (int)d.x; c1 = (int)d.y; c2 = (int)f.x; c3 = (int)f.y;
        } else {
            int4 rr = *reinterpret_cast<const int4*>((const int*)ei + e);
            r0 = rr.x; r1 = rr.y; r2 = rr.z; r3 = rr.w;
            int4 cc = *reinterpret_cast<const int4*>((const int*)ei + E + e);
            c0 = cc.x; c1 = cc.y; c2 = cc.z; c3 = cc.w;
        }
        int4* rcp = reinterpret_cast<int4*>(&g_rc[e]);
        rcp[0] = make_int4(r0, c0, r1, c1);
        rcp[1] = make_int4(r2, c2, r3, c3);
        atomicAdd(&g_deg[c0], s.x);
        atomicAdd(&g_deg[c1], s.y);
        atomicAdd(&g_deg[c2], s.z);
        atomicAdd(&g_deg[c3], s.w);
    } else {
        for (int k = e; k < E; k++) {
            float w = 1.0f / (1.0f + expf(-ew[k]));
            g_w[k] = w;
            int r = (int)load_idx(ei, (size_t)k, is64);
            int c = (int)load_idx(ei, (size_t)E + k, is64);
            g_rc[k] = make_int2(r, c);
            atomicAdd(&g_deg[c], w);
        }
    }
}

// ---------------------------------------------------------------------------
// 4) GEMM (slot 4 → profiled): xp = x @ W_sn ; out = xp/deg + bias ; stash xp, dis.
// ---------------------------------------------------------------------------
#define BK 32
__global__ void __launch_bounds__(128) k_gemm(const float* __restrict__ x,
                                              const float* __restrict__ bias,
                                              float* __restrict__ out, int N) {
    __shared__ float  xs[128][BK + 1];
    __shared__ float4 ws[BK * 16];  // W chunk: [BK][64] as float4

    int t = threadIdx.x;
    int row0 = blockIdx.x * 128;
    int row = row0 + t;

    float4 acc[16];
    #pragma unroll
    for (int j = 0; j < 16; j++) acc[j] = make_float4(0.f, 0.f, 0.f, 0.f);

    for (int kc = 0; kc < IN_F; kc += BK) {
        #pragma unroll
        for (int i = 0; i < 4; i++) {
            int idx = t + i * 128;
            ws[idx] = reinterpret_cast<const float4*>(g_Wsn)[kc * 16 + idx];
        }
        #pragma unroll
        for (int i = 0; i < 32; i++) {
            int idx = t + i * 128;
            int r = idx / BK;
            int kk = idx % BK;
            float v = (row0 + r < N) ? x[(size_t)(row0 + r) * IN_F + kc + kk] : 0.f;
            xs[r][kk] = v;
        }
        __syncthreads();
        #pragma unroll 4
        for (int kk = 0; kk < BK; kk++) {
            float xv = xs[t][kk];
            #pragma unroll
            for (int j = 0; j < 16; j++) {
                float4 w = ws[kk * 16 + j];
                acc[j].x += xv * w.x;
                acc[j].y += xv * w.y;
                acc[j].z += xv * w.z;
                acc[j].w += xv * w.w;
            }
        }
        __syncthreads();
    }

    if (row < N) {
        float d = g_deg[row];
        float dis = rsqrtf(d);
        float invd = 1.0f / d;
        g_dis[row] = dis;
        float4* xpp = reinterpret_cast<float4*>(&g_xp[(size_t)row * OUT_F]);
        float4* op = reinterpret_cast<float4*>(&out[(size_t)row * OUT_F]);
        const float4* b4 = reinterpret_cast<const float4*>(bias);
        #pragma unroll
        for (int j = 0; j < 16; j++) {
            xpp[j] = acc[j];
            float4 bb = b4[j];
            float4 o;
            o.x = acc[j].x * invd + bb.x;
            o.y = acc[j].y * invd + bb.y;
            o.z = acc[j].z * invd + bb.z;
            o.w = acc[j].w * invd + bb.w;
            op[j] = o;
        }
    }
}

// ---------------------------------------------------------------------------
// 5) Scatter (16 lanes/edge — 2 edges/warp keeps L1 wavefronts minimal):
//    out[col] += xp[row] * (dis[row]*w*dis[col])
// ---------------------------------------------------------------------------
__global__ void k_scatter(float* __restrict__ out, int E) {
    int gid = blockIdx.x * blockDim.x + threadIdx.x;
    int e = gid >> 4;
    if (e >= E) return;
    int lane = gid & 15;

    int2 rc = g_rc[e];                                  // broadcast (16 lanes same addr)
    float ne = g_w[e] * g_dis[rc.x] * g_dis[rc.y];      // broadcast loads

    float4 v = *reinterpret_cast<const float4*>(&g_xp[(size_t)rc.x * OUT_F + lane * 4]);
    float* dst = &out[(size_t)rc.y * OUT_F + lane * 4];
    asm volatile("red.global.add.v4.f32 [%0], {%1, %2, %3, %4};"
                 :: "l"(dst), "f"(v.x * ne), "f"(v.y * ne), "f"(v.z * ne), "f"(v.w * ne)
                 : "memory");
}

// ---------------------------------------------------------------------------
// Launch (5 launches; ncu captures #4 = k_gemm)
// ---------------------------------------------------------------------------
extern "C" void kernel_launch(void* const* d_in, const int* in_sizes, int n_in,
                              void* d_out, int out_size) {
    const float* x    = (const float*)d_in[0];
    const void*  ei   = d_in[1];
    const float* W    = (const float*)d_in[2];
    const float* bias = (const float*)d_in[3];
    const float* ew   = (const float*)d_in[4];
    const float* u    = (const float*)d_in[5];
    float*       out  = (float*)d_out;

    int N = in_sizes[0] / IN_F;
    int E = in_sizes[4];
    if (N > NMAX) N = NMAX;
    if (E > EMAX) E = EMAX;

    k_prep0<<<2, 256>>>((const unsigned int*)ei, 2 * E, W, u);
    k_deginit<<<(N + 255) / 256, 256>>>(N);
    k_deg<<<((E + 3) / 4 + 255) / 256, 256>>>(ei, ew, E);
    k_gemm<<<(N + 127) / 128, 128>>>(x, bias, out, N);
    k_scatter<<<((E * 16) + 255) / 256, 256>>>(out, E);
}

// round 8
// speedup vs baseline: 1.9232x; 1.3704x over previous
#include <cuda_runtime.h>
#include <math.h>

#define NMAX 100000
#define EMAX 600000
#define IN_F 128
#define OUT_F 64

// Scratch (static device globals — allocation-free per harness rules)
__device__ float g_Wsn[IN_F * OUT_F];
__device__ float g_xp[(size_t)NMAX * OUT_F];
__device__ float g_deg[NMAX];
__device__ float g_dis[NMAX];
__device__ float g_w[EMAX];
__device__ int2  g_rc[EMAX];
__device__ int   g_is64;   // 1 if edge_index is int64 on device, 0 if int32

__device__ __forceinline__ long long load_idx(const void* ei, size_t pos, int is64) {
    if (is64) return ((const long long*)ei)[pos];
    return (long long)(((const int*)ei)[pos]);
}

// ---------------------------------------------------------------------------
// 1) k_prep0: block 0 = dtype detect; block 1 = spectral norm -> g_Wsn
// ---------------------------------------------------------------------------
__global__ void k_prep0(const unsigned int* __restrict__ ei_u32, int nwords,
                        const float* __restrict__ W, const float* __restrict__ u) {
    int t = threadIdx.x;
    if (blockIdx.x == 0) {
        __shared__ int any;
        if (t == 0) any = 0;
        __syncthreads();
        int limit = nwords < 8192 ? nwords : 8192;
        for (int i = 1 + 2 * t; i < limit; i += 2 * blockDim.x)
            if (ei_u32[i] != 0u) any = 1;
        __syncthreads();
        if (t == 0) g_is64 = (any == 0) ? 1 : 0;
        return;
    }
    __shared__ float su[IN_F];
    __shared__ float sv[OUT_F];
    __shared__ float red[IN_F];

    if (t < IN_F) su[t] = u[t];
    __syncthreads();

    float tj = 0.f;
    if (t < OUT_F) {
        #pragma unroll 8
        for (int i = 0; i < IN_F; i++) tj += W[i * OUT_F + t] * su[i];
    }
    if (t < IN_F) red[t] = (t < OUT_F) ? tj * tj : 0.f;
    __syncthreads();
    for (int s = 64; s > 0; s >>= 1) {
        if (t < s) red[t] += red[t + s];
        __syncthreads();
    }
    float tn = sqrtf(red[0]) + 1e-12f;
    __syncthreads();
    if (t < OUT_F) sv[t] = tj / tn;
    __syncthreads();

    float wv = 0.f;
    if (t < IN_F) {
        #pragma unroll 8
        for (int j = 0; j < OUT_F; j++) wv += W[t * OUT_F + j] * sv[j];
        red[t] = wv * wv;
    }
    __syncthreads();
    for (int s = 64; s > 0; s >>= 1) {
        if (t < s) red[t] += red[t + s];
        __syncthreads();
    }
    float s2 = red[0];
    float sigma = s2 / (sqrtf(s2) + 1e-12f);
    float inv = 1.0f / sigma;
    for (int idx = t; idx < IN_F * OUT_F; idx += blockDim.x)
        g_Wsn[idx] = W[idx] * inv;
}

// ---------------------------------------------------------------------------
// 2) k_deginit: deg = 1.0 (self-loop)
// ---------------------------------------------------------------------------
__global__ void k_deginit(int N) {
    int i = blockIdx.x * blockDim.x + threadIdx.x;
    if (i < N) g_deg[i] = 1.0f;
}

// ---------------------------------------------------------------------------
// 3) k_deg: 4 edges/thread. g_w[e]=sigmoid(ew[e]); deg[col]+=w; pack g_rc.
// ---------------------------------------------------------------------------
__global__ void k_deg(const void* __restrict__ ei, const float* __restrict__ ew, int E) {
    int e = (blockIdx.x * blockDim.x + threadIdx.x) * 4;
    if (e >= E) return;
    int is64 = g_is64;

    if (e + 3 < E) {
        float4 w4 = *reinterpret_cast<const float4*>(ew + e);
        float4 s;
        s.x = 1.0f / (1.0f + expf(-w4.x));
        s.y = 1.0f / (1.0f + expf(-w4.y));
        s.z = 1.0f / (1.0f + expf(-w4.z));
        s.w = 1.0f / (1.0f + expf(-w4.w));
        *reinterpret_cast<float4*>(g_w + e) = s;
        int r0, r1, r2, r3, c0, c1, c2, c3;
        if (is64) {
            const longlong2* pr = reinterpret_cast<const longlong2*>((const long long*)ei + e);
            longlong2 a = pr[0], bq = pr[1];
            r0 = (int)a.x; r1 = (int)a.y; r2 = (int)bq.x; r3 = (int)bq.y;
            const longlong2* pc = reinterpret_cast<const longlong2*>((const long long*)ei + E + e);
            longlong2 d = pc[0], f = pc[1];
            c0 = (int)d.x; c1 = (int)d.y; c2 = (int)f.x; c3 = (int)f.y;
        } else {
            int4 rr = *reinterpret_cast<const int4*>((const int*)ei + e);
            r0 = rr.x; r1 = rr.y; r2 = rr.z; r3 = rr.w;
            int4 cc = *reinterpret_cast<const int4*>((const int*)ei + E + e);
            c0 = cc.x; c1 = cc.y; c2 = cc.z; c3 = cc.w;
        }
        int4* rcp = reinterpret_cast<int4*>(&g_rc[e]);
        rcp[0] = make_int4(r0, c0, r1, c1);
        rcp[1] = make_int4(r2, c2, r3, c3);
        atomicAdd(&g_deg[c0], s.x);
        atomicAdd(&g_deg[c1], s.y);
        atomicAdd(&g_deg[c2], s.z);
        atomicAdd(&g_deg[c3], s.w);
    } else {
        for (int k = e; k < E; k++) {
            float w = 1.0f / (1.0f + expf(-ew[k]));
            g_w[k] = w;
            int r = (int)load_idx(ei, (size_t)k, is64);
            int c = (int)load_idx(ei, (size_t)E + k, is64);
            g_rc[k] = make_int2(r, c);
            atomicAdd(&g_deg[c], w);
        }
    }
}

// ---------------------------------------------------------------------------
// 4) GEMM v2 (register-blocked; slot 4 → profiled):
//    xp = x @ W_sn ; out = xp/deg + bias ; stash xp, dis.
//    256 thr/block; thread tile 8 rows x 4 cols; block tile 128 x 64.
// ---------------------------------------------------------------------------
#define BK 32
#define XS_STRIDE 132   // 128 + 4: keeps kk*132 + 8*ty 16B-aligned for LDS.128
#define WS_STRIDE 17    // in float4 units (68 floats)

__global__ void __launch_bounds__(256) k_gemm(const float* __restrict__ x,
                                              const float* __restrict__ bias,
                                              float* __restrict__ out, int N) {
    __shared__ float  xs[BK * XS_STRIDE];      // transposed x tile: [k][row]
    __shared__ float4 ws[BK * WS_STRIDE];      // W tile: [k][16 float4]

    int t = threadIdx.x;
    int tx = t & 15;          // 16 col-groups of 4
    int ty = t >> 4;          // 16 row-groups of 8
    int row0 = blockIdx.x * 128;

    float4 acc[8];
    #pragma unroll
    for (int r = 0; r < 8; r++) acc[r] = make_float4(0.f, 0.f, 0.f, 0.f);

    const float4* Wg = reinterpret_cast<const float4*>(g_Wsn);

    for (int kc = 0; kc < IN_F; kc += BK) {
        // Load W chunk: BK*16 float4 = 512; 2 per thread
        #pragma unroll
        for (int i = 0; i < 2; i++) {
            int idx = t + i * 256;
            int kk = idx >> 4;
            int c4 = idx & 15;
            ws[kk * WS_STRIDE + c4] = Wg[(kc + kk) * 16 + idx % 16 - (idx & 15) + c4];
        }
        // Load x tile 128 rows x BK, transposed into xs[k][row]
        #pragma unroll
        for (int i = 0; i < 4; i++) {
            int idx = t + i * 256;            // 0..1023 float4 slots
            int r = idx >> 3;                 // row 0..127
            int k4 = (idx & 7) << 2;          // k offset 0,4,...,28
            float4 v = make_float4(0.f, 0.f, 0.f, 0.f);
            if (row0 + r < N)
                v = *reinterpret_cast<const float4*>(&x[(size_t)(row0 + r) * IN_F + kc + k4]);
            xs[(k4 + 0) * XS_STRIDE + r] = v.x;
            xs[(k4 + 1) * XS_STRIDE + r] = v.y;
            xs[(k4 + 2) * XS_STRIDE + r] = v.z;
            xs[(k4 + 3) * XS_STRIDE + r] = v.w;
        }
        __syncthreads();

        #pragma unroll 8
        for (int kk = 0; kk < BK; kk++) {
            float4 a0 = *reinterpret_cast<const float4*>(&xs[kk * XS_STRIDE + ty * 8]);
            float4 a1 = *reinterpret_cast<const float4*>(&xs[kk * XS_STRIDE + ty * 8 + 4]);
            float4 b  = ws[kk * WS_STRIDE + tx];
            acc[0].x += a0.x * b.x; acc[0].y += a0.x * b.y; acc[0].z += a0.x * b.z; acc[0].w += a0.x * b.w;
            acc[1].x += a0.y * b.x; acc[1].y += a0.y * b.y; acc[1].z += a0.y * b.z; acc[1].w += a0.y * b.w;
            acc[2].x += a0.z * b.x; acc[2].y += a0.z * b.y; acc[2].z += a0.z * b.z; acc[2].w += a0.z * b.w;
            acc[3].x += a0.w * b.x; acc[3].y += a0.w * b.y; acc[3].z += a0.w * b.z; acc[3].w += a0.w * b.w;
            acc[4].x += a1.x * b.x; acc[4].y += a1.x * b.y; acc[4].z += a1.x * b.z; acc[4].w += a1.x * b.w;
            acc[5].x += a1.y * b.x; acc[5].y += a1.y * b.y; acc[5].z += a1.y * b.z; acc[5].w += a1.y * b.w;
            acc[6].x += a1.z * b.x; acc[6].y += a1.z * b.y; acc[6].z += a1.z * b.z; acc[6].w += a1.z * b.w;
            acc[7].x += a1.w * b.x; acc[7].y += a1.w * b.y; acc[7].z += a1.w * b.z; acc[7].w += a1.w * b.w;
        }
        __syncthreads();
    }

    // Epilogue: rows ty*8..ty*8+7, cols tx*4..tx*4+3
    float4 bb = reinterpret_cast<const float4*>(bias)[tx];
    #pragma unroll
    for (int r = 0; r < 8; r++) {
        int row = row0 + ty * 8 + r;
        if (row >= N) break;
        float d = g_deg[row];          // broadcast across the 16 tx threads
        float dis = rsqrtf(d);
        float invd = dis * dis;        // 1/d without RCP
        if (tx == 0) g_dis[row] = dis;
        float4 a = acc[r];
        *reinterpret_cast<float4*>(&g_xp[(size_t)row * OUT_F + tx * 4]) = a;
        float4 o = make_float4(fmaf(a.x, invd, bb.x), fmaf(a.y, invd, bb.y),
                               fmaf(a.z, invd, bb.z), fmaf(a.w, invd, bb.w));
        *reinterpret_cast<float4*>(&out[(size_t)row * OUT_F + tx * 4]) = o;
    }
}

// ---------------------------------------------------------------------------
// 5) Scatter (16 lanes/edge — 2 edges/warp keeps L1 wavefronts minimal)
// ---------------------------------------------------------------------------
__global__ void k_scatter(float* __restrict__ out, int E) {
    int gid = blockIdx.x * blockDim.x + threadIdx.x;
    int e = gid >> 4;
    if (e >= E) return;
    int lane = gid & 15;

    int2 rc = g_rc[e];                                  // broadcast (16 lanes same addr)
    float ne = g_w[e] * g_dis[rc.x] * g_dis[rc.y];      // broadcast loads

    float4 v = *reinterpret_cast<const float4*>(&g_xp[(size_t)rc.x * OUT_F + lane * 4]);
    float* dst = &out[(size_t)rc.y * OUT_F + lane * 4];
    asm volatile("red.global.add.v4.f32 [%0], {%1, %2, %3, %4};"
                 :: "l"(dst), "f"(v.x * ne), "f"(v.y * ne), "f"(v.z * ne), "f"(v.w * ne)
                 : "memory");
}

// ---------------------------------------------------------------------------
// Launch (5 launches; ncu captures #4 = k_gemm)
// ---------------------------------------------------------------------------
extern "C" void kernel_launch(void* const* d_in, const int* in_sizes, int n_in,
                              void* d_out, int out_size) {
    const float* x    = (const float*)d_in[0];
    const void*  ei   = d_in[1];
    const float* W    = (const float*)d_in[2];
    const float* bias = (const float*)d_in[3];
    const float* ew   = (const float*)d_in[4];
    const float* u    = (const float*)d_in[5];
    float*       out  = (float*)d_out;

    int N = in_sizes[0] / IN_F;
    int E = in_sizes[4];
    if (N > NMAX) N = NMAX;
    if (E > EMAX) E = EMAX;

    k_prep0<<<2, 256>>>((const unsigned int*)ei, 2 * E, W, u);
    k_deginit<<<(N + 255) / 256, 256>>>(N);
    k_deg<<<((E + 3) / 4 + 255) / 256, 256>>>(ei, ew, E);
    k_gemm<<<(N + 127) / 128, 256>>>(x, bias, out, N);
    k_scatter<<<((E * 16) + 255) / 256, 256>>>(out, E);
}

// round 11
// speedup vs baseline: 1.9860x; 1.0326x over previous
#include <cuda_runtime.h>
#include <math.h>
#include <stdint.h>

#define NMAX 100000
#define EMAX 600000
#define IN_F 128
#define OUT_F 64

// Scratch (static device globals — allocation-free per harness rules)
__device__ float g_Wsn[IN_F * OUT_F];
__device__ float g_xp[(size_t)NMAX * OUT_F];
__device__ float g_deg[NMAX];
__device__ float g_w[EMAX];
__device__ int2  g_rc[EMAX];
__device__ int   g_is64;

__device__ __forceinline__ long long load_idx(const void* ei, size_t pos, int is64) {
    if (is64) return ((const long long*)ei)[pos];
    return (long long)(((const int*)ei)[pos]);
}

// ---------------------------------------------------------------------------
// 1) k_prep (block-switched, all paths independent):
//    b0: dtype detect | b1: spectral norm -> g_Wsn | deg=1 init | out=0 init
// ---------------------------------------------------------------------------
__global__ void k_prep(const unsigned int* __restrict__ ei_u32, int nwords,
                       const float* __restrict__ W, const float* __restrict__ u,
                       float* __restrict__ out, int out_size,
                       int N, int nbDeg) {
    int t = threadIdx.x;
    int b = blockIdx.x;

    if (b == 0) {
        __shared__ int any;
        if (t == 0) any = 0;
        __syncthreads();
        int limit = nwords < 8192 ? nwords : 8192;
        for (int i = 1 + 2 * t; i < limit; i += 2 * blockDim.x)
            if (ei_u32[i] != 0u) any = 1;
        __syncthreads();
        if (t == 0) g_is64 = (any == 0) ? 1 : 0;
        return;
    }
    if (b == 1) {
        __shared__ float su[IN_F];
        __shared__ float sv[OUT_F];
        __shared__ float red[IN_F];

        if (t < IN_F) su[t] = u[t];
        __syncthreads();

        float tj = 0.f;
        if (t < OUT_F) {
            #pragma unroll 8
            for (int i = 0; i < IN_F; i++) tj += W[i * OUT_F + t] * su[i];
        }
        if (t < IN_F) red[t] = (t < OUT_F) ? tj * tj : 0.f;
        __syncthreads();
        for (int s = 64; s > 0; s >>= 1) {
            if (t < s) red[t] += red[t + s];
            __syncthreads();
        }
        float tn = sqrtf(red[0]) + 1e-12f;
        __syncthreads();
        if (t < OUT_F) sv[t] = tj / tn;
        __syncthreads();

        float wv = 0.f;
        if (t < IN_F) {
            #pragma unroll 8
            for (int j = 0; j < OUT_F; j++) wv += W[t * OUT_F + j] * sv[j];
            red[t] = wv * wv;
        }
        __syncthreads();
        for (int s = 64; s > 0; s >>= 1) {
            if (t < s) red[t] += red[t + s];
            __syncthreads();
        }
        float s2 = red[0];
        float sigma = s2 / (sqrtf(s2) + 1e-12f);
        float inv = 1.0f / sigma;
        for (int idx = t; idx < IN_F * OUT_F; idx += blockDim.x)
            g_Wsn[idx] = W[idx] * inv;
        return;
    }
    if (b < 2 + nbDeg) {
        int i = (b - 2) * blockDim.x + t;
        if (i < N) g_deg[i] = 1.0f;
        return;
    }
    // zero out (float4 granularity; out_size divisible by 4 for OUT_F=64)
    int idx = (b - 2 - nbDeg) * blockDim.x + t;
    int n4 = out_size >> 2;
    if (idx < n4)
        reinterpret_cast<float4*>(out)[idx] = make_float4(0.f, 0.f, 0.f, 0.f);
}

// ---------------------------------------------------------------------------
// 2) k_fused: deg-atomic blocks (memory-bound) overlap GEMM blocks (FMA-bound)
//    deg path: g_w[e]=sigmoid(ew); deg[col]+=w; pack g_rc (4 edges/thread)
//    gemm path (R8 core): g_xp = x @ W_sn  (no deg dependency, no out writes)
// ---------------------------------------------------------------------------
#define BK 32
#define XS_STRIDE 132
#define WS_STRIDE 17

__global__ void __launch_bounds__(256) k_fused(const float* __restrict__ x,
                                               const void* __restrict__ ei,
                                               const float* __restrict__ ew,
                                               int N, int E, int nbDeg) {
    int t = threadIdx.x;
    int b = blockIdx.x;

    if (b < nbDeg) {
        // ---- deg path ----
        int e = (b * blockDim.x + t) * 4;
        if (e >= E) return;
        int is64 = g_is64;
        if (e + 3 < E) {
            float4 w4 = *reinterpret_cast<const float4*>(ew + e);
            float4 s;
            s.x = 1.0f / (1.0f + expf(-w4.x));
            s.y = 1.0f / (1.0f + expf(-w4.y));
            s.z = 1.0f / (1.0f + expf(-w4.z));
            s.w = 1.0f / (1.0f + expf(-w4.w));
            *reinterpret_cast<float4*>(g_w + e) = s;
            int r0, r1, r2, r3, c0, c1, c2, c3;
            if (is64) {
                const longlong2* pr = reinterpret_cast<const longlong2*>((const long long*)ei + e);
                longlong2 a = pr[0], bq = pr[1];
                r0 = (int)a.x; r1 = (int)a.y; r2 = (int)bq.x; r3 = (int)bq.y;
                const longlong2* pc = reinterpret_cast<const longlong2*>((const long long*)ei + E + e);
                longlong2 d = pc[0], f = pc[1];
                c0 = (int)d.x; c1 = (int)d.y; c2 = (int)f.x; c3 = (int)f.y;
            } else {
                int4 rr = *reinterpret_cast<const int4*>((const int*)ei + e);
                r0 = rr.x; r1 = rr.y; r2 = rr.z; r3 = rr.w;
                int4 cc = *reinterpret_cast<const int4*>((const int*)ei + E + e);
                c0 = cc.x; c1 = cc.y; c2 = cc.z; c3 = cc.w;
            }
            int4* rcp = reinterpret_cast<int4*>(&g_rc[e]);
            rcp[0] = make_int4(r0, c0, r1, c1);
            rcp[1] = make_int4(r2, c2, r3, c3);
            atomicAdd(&g_deg[c0], s.x);
            atomicAdd(&g_deg[c1], s.y);
            atomicAdd(&g_deg[c2], s.z);
            atomicAdd(&g_deg[c3], s.w);
        } else {
            for (int k = e; k < E; k++) {
                float w = 1.0f / (1.0f + expf(-ew[k]));
                g_w[k] = w;
                int r = (int)load_idx(ei, (size_t)k, is64);
                int c = (int)load_idx(ei, (size_t)E + k, is64);
                g_rc[k] = make_int2(r, c);
                atomicAdd(&g_deg[c], w);
            }
        }
        return;
    }

    // ---- gemm path ----
    __shared__ float  xs[BK * XS_STRIDE];
    __shared__ float4 ws[BK * WS_STRIDE];

    int gb = b - nbDeg;
    int tx = t & 15;
    int ty = t >> 4;
    int row0 = gb * 128;

    float4 acc[8];
    #pragma unroll
    for (int r = 0; r < 8; r++) acc[r] = make_float4(0.f, 0.f, 0.f, 0.f);

    const float4* Wg = reinterpret_cast<const float4*>(g_Wsn);

    for (int kc = 0; kc < IN_F; kc += BK) {
        #pragma unroll
        for (int i = 0; i < 2; i++) {
            int idx = t + i * 256;
            int kk = idx >> 4;
            int c4 = idx & 15;
            ws[kk * WS_STRIDE + c4] = Wg[(kc + kk) * 16 + c4];
        }
        #pragma unroll
        for (int i = 0; i < 4; i++) {
            int idx = t + i * 256;
            int r = idx >> 3;
            int k4 = (idx & 7) << 2;
            float4 v = make_float4(0.f, 0.f, 0.f, 0.f);
            if (row0 + r < N)
                v = *reinterpret_cast<const float4*>(&x[(size_t)(row0 + r) * IN_F + kc + k4]);
            xs[(k4 + 0) * XS_STRIDE + r] = v.x;
            xs[(k4 + 1) * XS_STRIDE + r] = v.y;
            xs[(k4 + 2) * XS_STRIDE + r] = v.z;
            xs[(k4 + 3) * XS_STRIDE + r] = v.w;
        }
        __syncthreads();

        #pragma unroll 8
        for (int kk = 0; kk < BK; kk++) {
            float4 a0 = *reinterpret_cast<const float4*>(&xs[kk * XS_STRIDE + ty * 8]);
            float4 a1 = *reinterpret_cast<const float4*>(&xs[kk * XS_STRIDE + ty * 8 + 4]);
            float4 bb = ws[kk * WS_STRIDE + tx];
            acc[0].x += a0.x * bb.x; acc[0].y += a0.x * bb.y; acc[0].z += a0.x * bb.z; acc[0].w += a0.x * bb.w;
            acc[1].x += a0.y * bb.x; acc[1].y += a0.y * bb.y; acc[1].z += a0.y * bb.z; acc[1].w += a0.y * bb.w;
            acc[2].x += a0.z * bb.x; acc[2].y += a0.z * bb.y; acc[2].z += a0.z * bb.z; acc[2].w += a0.z * bb.w;
            acc[3].x += a0.w * bb.x; acc[3].y += a0.w * bb.y; acc[3].z += a0.w * bb.z; acc[3].w += a0.w * bb.w;
            acc[4].x += a1.x * bb.x; acc[4].y += a1.x * bb.y; acc[4].z += a1.x * bb.z; acc[4].w += a1.x * bb.w;
            acc[5].x += a1.y * bb.x; acc[5].y += a1.y * bb.y; acc[5].z += a1.y * bb.z; acc[5].w += a1.y * bb.w;
            acc[6].x += a1.z * bb.x; acc[6].y += a1.z * bb.y; acc[6].z += a1.z * bb.z; acc[6].w += a1.z * bb.w;
            acc[7].x += a1.w * bb.x; acc[7].y += a1.w * bb.y; acc[7].z += a1.w * bb.z; acc[7].w += a1.w * bb.w;
        }
        __syncthreads();
    }

    #pragma unroll
    for (int r = 0; r < 8; r++) {
        int row = row0 + ty * 8 + r;
        if (row >= N) break;
        *reinterpret_cast<float4*>(&g_xp[(size_t)row * OUT_F + tx * 4]) = acc[r];
    }
}

// ---------------------------------------------------------------------------
// 3) k_scatter (block-switched):
//    edge blocks: out[col] += xp[row] * (rsqrt(deg_r)*w*rsqrt(deg_c)), 16 lanes/edge
//    self blocks: out[row]  += xp[row]/deg + bias   (RED into zeroed out)
// ---------------------------------------------------------------------------
__global__ void k_scatter(const float* __restrict__ bias, float* __restrict__ out,
                          int N, int E, int nbEdge) {
    int t = threadIdx.x;
    int b = blockIdx.x;

    if (b < nbEdge) {
        int gid = b * blockDim.x + t;
        int e = gid >> 4;
        if (e >= E) return;
        int lane = gid & 15;

        int2 rc = g_rc[e];                                       // broadcast
        float ne = g_w[e] * rsqrtf(g_deg[rc.x]) * rsqrtf(g_deg[rc.y]);

        float4 v = *reinterpret_cast<const float4*>(&g_xp[(size_t)rc.x * OUT_F + lane * 4]);
        float* dst = &out[(size_t)rc.y * OUT_F + lane * 4];
        asm volatile("red.global.add.v4.f32 [%0], {%1, %2, %3, %4};"
                     :: "l"(dst), "f"(v.x * ne), "f"(v.y * ne), "f"(v.z * ne), "f"(v.w * ne)
                     : "memory");
        return;
    }

    // self-loop blocks
    int idx = (b - nbEdge) * blockDim.x + t;   // float4 index over [N*16)
    int row = idx >> 4;
    if (row >= N) return;
    int c4 = idx & 15;
    float invd = 1.0f / g_deg[row];            // broadcast across 16 threads
    float4 v = *reinterpret_cast<const float4*>(&g_xp[(size_t)row * OUT_F + c4 * 4]);
    float4 bb = reinterpret_cast<const float4*>(bias)[c4];
    float* dst = &out[(size_t)row * OUT_F + c4 * 4];
    asm volatile("red.global.add.v4.f32 [%0], {%1, %2, %3, %4};"
                 :: "l"(dst), "f"(fmaf(v.x, invd, bb.x)), "f"(fmaf(v.y, invd, bb.y)),
                    "f"(fmaf(v.z, invd, bb.z)), "f"(fmaf(v.w, invd, bb.w))
                 : "memory");
}

// ---------------------------------------------------------------------------
// Launch (3 launches)
// ---------------------------------------------------------------------------
extern "C" void kernel_launch(void* const* d_in, const int* in_sizes, int n_in,
                              void* d_out, int out_size) {
    const float* x    = (const float*)d_in[0];
    const void*  ei   = d_in[1];
    const float* W    = (const float*)d_in[2];
    const float* bias = (const float*)d_in[3];
    const float* ew   = (const float*)d_in[4];
    const float* u    = (const float*)d_in[5];
    float*       out  = (float*)d_out;

    int N = in_sizes[0] / IN_F;
    int E = in_sizes[4];
    if (N > NMAX) N = NMAX;
    if (E > EMAX) E = EMAX;

    int nbDegInit = (N + 255) / 256;
    int nbZero    = ((out_size >> 2) + 255) / 256;
    k_prep<<<2 + nbDegInit + nbZero, 256>>>((const unsigned int*)ei, 2 * E, W, u,
                                            out, out_size, N, nbDegInit);

    int nbDeg  = ((E + 3) / 4 + 255) / 256;
    int nbGemm = (N + 127) / 128;
    k_fused<<<nbDeg + nbGemm, 256>>>(x, ei, ew, N, E, nbDeg);

    int nbEdge = (E * 16 + 255) / 256;
    int nbSelf = (N * 16 + 255) / 256;
    k_scatter<<<nbEdge + nbSelf, 256>>>(bias, out, N, E, nbEdge);
}

// round 13
// speedup vs baseline: 2.0475x; 1.0310x over previous
#include <cuda_runtime.h>
#include <math.h>
#include <stdint.h>

#define NMAX 100000
#define EMAX 600000
#define IN_F 128
#define OUT_F 64

// Scratch (static device globals — allocation-free per harness rules)
__device__ float g_Wsn[IN_F * OUT_F];
__device__ float g_xp[(size_t)NMAX * OUT_F];
__device__ float g_deg[NMAX];
__device__ float g_w[EMAX];
__device__ int2  g_rc[EMAX];
__device__ int   g_is64;

__device__ __forceinline__ long long load_idx(const void* ei, size_t pos, int is64) {
    if (is64) return ((const long long*)ei)[pos];
    return (long long)(((const int*)ei)[pos]);
}

// ---------------------------------------------------------------------------
// 1) k_prep (block-switched, all paths independent):
//    b0: dtype detect | b1: spectral norm -> g_Wsn | deg=1 init | out=0 init
// ---------------------------------------------------------------------------
__global__ void k_prep(const unsigned int* __restrict__ ei_u32, int nwords,
                       const float* __restrict__ W, const float* __restrict__ u,
                       float* __restrict__ out, int out_size,
                       int N, int nbDeg) {
    int t = threadIdx.x;
    int b = blockIdx.x;

    if (b == 0) {
        __shared__ int any;
        if (t == 0) any = 0;
        __syncthreads();
        int limit = nwords < 8192 ? nwords : 8192;
        for (int i = 1 + 2 * t; i < limit; i += 2 * blockDim.x)
            if (ei_u32[i] != 0u) any = 1;
        __syncthreads();
        if (t == 0) g_is64 = (any == 0) ? 1 : 0;
        return;
    }
    if (b == 1) {
        // Spectral norm, parallelized across all 256 threads.
        __shared__ float su[IN_F];
        __shared__ float sv[OUT_F];
        __shared__ float red1[4][OUT_F];   // matvec1 partials
        __shared__ float red2[2][IN_F];    // matvec2 partials
        __shared__ float rsum[8];
        __shared__ float s_tn, s_inv;

        if (t < IN_F) su[t] = u[t];
        __syncthreads();

        // Matvec1: tj[j] = sum_i W[i*64+j] * u[i]; thread (j = t&63, half = t>>6)
        {
            int j = t & 63;
            int half = t >> 6;             // 0..3, i-range [half*32, half*32+32)
            float p = 0.f;
            int i0 = half * 32;
            #pragma unroll 8
            for (int i = 0; i < 32; i++) p += W[(i0 + i) * OUT_F + j] * su[i0 + i];
            red1[half][j] = p;
        }
        __syncthreads();

        // tj + norm^2 reduction (threads 0..63)
        float tj = 0.f;
        if (t < OUT_F) {
            tj = red1[0][t] + red1[1][t] + red1[2][t] + red1[3][t];
            float sq = tj * tj;
            #pragma unroll
            for (int o = 16; o > 0; o >>= 1) sq += __shfl_down_sync(0xffffffffu, sq, o);
            if ((t & 31) == 0) rsum[t >> 5] = sq;
        }
        __syncthreads();
        if (t == 0) s_tn = sqrtf(rsum[0] + rsum[1]) + 1e-12f;
        __syncthreads();
        if (t < OUT_F) sv[t] = tj / s_tn;
        __syncthreads();

        // Matvec2: wv[i] = sum_j W[i*64+j] * sv[j]; thread (i = t&127, half = t>>7)
        {
            int i = t & 127;
            int half = t >> 7;             // 0..1, j-range [half*32, half*32+32)
            float p = 0.f;
            int j0 = half * 32;
            #pragma unroll 8
            for (int j = 0; j < 32; j++) p += W[i * OUT_F + j0 + j] * sv[j0 + j];
            red2[half][i] = p;
        }
        __syncthreads();

        // ||Wv||^2 reduction (threads 0..127)
        if (t < IN_F) {
            float wv = red2[0][t] + red2[1][t];
            float sq = wv * wv;
            #pragma unroll
            for (int o = 16; o > 0; o >>= 1) sq += __shfl_down_sync(0xffffffffu, sq, o);
            if ((t & 31) == 0) rsum[t >> 5] = sq;
        }
        __syncthreads();
        if (t == 0) {
            float s2 = rsum[0] + rsum[1] + rsum[2] + rsum[3];
            float sigma = s2 / (sqrtf(s2) + 1e-12f);
            s_inv = 1.0f / sigma;
        }
        __syncthreads();

        // Scale W -> g_Wsn (coalesced float4)
        {
            float inv = s_inv;
            const float4* W4 = reinterpret_cast<const float4*>(W);
            float4* O4 = reinterpret_cast<float4*>(g_Wsn);
            #pragma unroll
            for (int i = 0; i < 8; i++) {
                int idx = t + i * 256;     // 2048 float4
                float4 v = W4[idx];
                O4[idx] = make_float4(v.x * inv, v.y * inv, v.z * inv, v.w * inv);
            }
        }
        return;
    }
    if (b < 2 + nbDeg) {
        int i = (b - 2) * blockDim.x + t;
        if (i < N) g_deg[i] = 1.0f;
        return;
    }
    // zero out: 4 float4 per thread => each block covers 1024 float4
    int base = ((b - 2 - nbDeg) * blockDim.x + t) * 4;
    int n4 = out_size >> 2;
    float4* o4 = reinterpret_cast<float4*>(out);
    #pragma unroll
    for (int i = 0; i < 4; i++) {
        int idx = base + i;
        if (idx < n4) o4[idx] = make_float4(0.f, 0.f, 0.f, 0.f);
    }
}

// ---------------------------------------------------------------------------
// 2) k_fused: deg-atomic blocks (memory-bound) overlap GEMM blocks (FMA-bound)
// ---------------------------------------------------------------------------
#define BK 32
#define XS_STRIDE 132
#define WS_STRIDE 17

__global__ void __launch_bounds__(256) k_fused(const float* __restrict__ x,
                                               const void* __restrict__ ei,
                                               const float* __restrict__ ew,
                                               int N, int E, int nbDeg) {
    int t = threadIdx.x;
    int b = blockIdx.x;

    if (b < nbDeg) {
        // ---- deg path ----
        int e = (b * blockDim.x + t) * 4;
        if (e >= E) return;
        int is64 = g_is64;
        if (e + 3 < E) {
            float4 w4 = *reinterpret_cast<const float4*>(ew + e);
            float4 s;
            s.x = 1.0f / (1.0f + expf(-w4.x));
            s.y = 1.0f / (1.0f + expf(-w4.y));
            s.z = 1.0f / (1.0f + expf(-w4.z));
            s.w = 1.0f / (1.0f + expf(-w4.w));
            *reinterpret_cast<float4*>(g_w + e) = s;
            int r0, r1, r2, r3, c0, c1, c2, c3;
            if (is64) {
                const longlong2* pr = reinterpret_cast<const longlong2*>((const long long*)ei + e);
                longlong2 a = pr[0], bq = pr[1];
                r0 = (int)a.x; r1 = (int)a.y; r2 = (int)bq.x; r3 = (int)bq.y;
                const longlong2* pc = reinterpret_cast<const longlong2*>((const long long*)ei + E + e);
                longlong2 d = pc[0], f = pc[1];
                c0 = (int)d.x; c1 = (int)d.y; c2 = (int)f.x; c3 = (int)f.y;
            } else {
                int4 rr = *reinterpret_cast<const int4*>((const int*)ei + e);
                r0 = rr.x; r1 = rr.y; r2 = rr.z; r3 = rr.w;
                int4 cc = *reinterpret_cast<const int4*>((const int*)ei + E + e);
                c0 = cc.x; c1 = cc.y; c2 = cc.z; c3 = cc.w;
            }
            int4* rcp = reinterpret_cast<int4*>(&g_rc[e]);
            rcp[0] = make_int4(r0, c0, r1, c1);
            rcp[1] = make_int4(r2, c2, r3, c3);
            atomicAdd(&g_deg[c0], s.x);
            atomicAdd(&g_deg[c1], s.y);
            atomicAdd(&g_deg[c2], s.z);
            atomicAdd(&g_deg[c3], s.w);
        } else {
            for (int k = e; k < E; k++) {
                float w = 1.0f / (1.0f + expf(-ew[k]));
                g_w[k] = w;
                int r = (int)load_idx(ei, (size_t)k, is64);
                int c = (int)load_idx(ei, (size_t)E + k, is64);
                g_rc[k] = make_int2(r, c);
                atomicAdd(&g_deg[c], w);
            }
        }
        return;
    }

    // ---- gemm path ----
    __shared__ float  xs[BK * XS_STRIDE];
    __shared__ float4 ws[BK * WS_STRIDE];

    int gb = b - nbDeg;
    int tx = t & 15;
    int ty = t >> 4;
    int row0 = gb * 128;

    float4 acc[8];
    #pragma unroll
    for (int r = 0; r < 8; r++) acc[r] = make_float4(0.f, 0.f, 0.f, 0.f);

    const float4* Wg = reinterpret_cast<const float4*>(g_Wsn);

    for (int kc = 0; kc < IN_F; kc += BK) {
        #pragma unroll
        for (int i = 0; i < 2; i++) {
            int idx = t + i * 256;
            int kk = idx >> 4;
            int c4 = idx & 15;
            ws[kk * WS_STRIDE + c4] = Wg[(kc + kk) * 16 + c4];
        }
        #pragma unroll
        for (int i = 0; i < 4; i++) {
            int idx = t + i * 256;
            int r = idx >> 3;
            int k4 = (idx & 7) << 2;
            float4 v = make_float4(0.f, 0.f, 0.f, 0.f);
            if (row0 + r < N)
                v = *reinterpret_cast<const float4*>(&x[(size_t)(row0 + r) * IN_F + kc + k4]);
            xs[(k4 + 0) * XS_STRIDE + r] = v.x;
            xs[(k4 + 1) * XS_STRIDE + r] = v.y;
            xs[(k4 + 2) * XS_STRIDE + r] = v.z;
            xs[(k4 + 3) * XS_STRIDE + r] = v.w;
        }
        __syncthreads();

        #pragma unroll 8
        for (int kk = 0; kk < BK; kk++) {
            float4 a0 = *reinterpret_cast<const float4*>(&xs[kk * XS_STRIDE + ty * 8]);
            float4 a1 = *reinterpret_cast<const float4*>(&xs[kk * XS_STRIDE + ty * 8 + 4]);
            float4 bb = ws[kk * WS_STRIDE + tx];
            acc[0].x += a0.x * bb.x; acc[0].y += a0.x * bb.y; acc[0].z += a0.x * bb.z; acc[0].w += a0.x * bb.w;
            acc[1].x += a0.y * bb.x; acc[1].y += a0.y * bb.y; acc[1].z += a0.y * bb.z; acc[1].w += a0.y * bb.w;
            acc[2].x += a0.z * bb.x; acc[2].y += a0.z * bb.y; acc[2].z += a0.z * bb.z; acc[2].w += a0.z * bb.w;
            acc[3].x += a0.w * bb.x; acc[3].y += a0.w * bb.y; acc[3].z += a0.w * bb.z; acc[3].w += a0.w * bb.w;
            acc[4].x += a1.x * bb.x; acc[4].y += a1.x * bb.y; acc[4].z += a1.x * bb.z; acc[4].w += a1.x * bb.w;
            acc[5].x += a1.y * bb.x; acc[5].y += a1.y * bb.y; acc[5].z += a1.y * bb.z; acc[5].w += a1.y * bb.w;
            acc[6].x += a1.z * bb.x; acc[6].y += a1.z * bb.y; acc[6].z += a1.z * bb.z; acc[6].w += a1.z * bb.w;
            acc[7].x += a1.w * bb.x; acc[7].y += a1.w * bb.y; acc[7].z += a1.w * bb.z; acc[7].w += a1.w * bb.w;
        }
        __syncthreads();
    }

    #pragma unroll
    for (int r = 0; r < 8; r++) {
        int row = row0 + ty * 8 + r;
        if (row >= N) break;
        *reinterpret_cast<float4*>(&g_xp[(size_t)row * OUT_F + tx * 4]) = acc[r];
    }
}

// ---------------------------------------------------------------------------
// 3) k_scatter (block-switched):
//    edge blocks: out[col] += xp[row] * (rsqrt(deg_r)*w*rsqrt(deg_c)), 16 lanes/edge
//    self blocks: out[row]  += xp[row]/deg + bias   (RED into zeroed out)
// ---------------------------------------------------------------------------
__global__ void k_scatter(const float* __restrict__ bias, float* __restrict__ out,
                          int N, int E, int nbEdge) {
    int t = threadIdx.x;
    int b = blockIdx.x;

    if (b < nbEdge) {
        int gid = b * blockDim.x + t;
        int e = gid >> 4;
        if (e >= E) return;
        int lane = gid & 15;

        int2 rc = g_rc[e];                                       // broadcast
        float ne = g_w[e] * rsqrtf(g_deg[rc.x]) * rsqrtf(g_deg[rc.y]);

        float4 v = *reinterpret_cast<const float4*>(&g_xp[(size_t)rc.x * OUT_F + lane * 4]);
        float* dst = &out[(size_t)rc.y * OUT_F + lane * 4];
        asm volatile("red.global.add.v4.f32 [%0], {%1, %2, %3, %4};"
                     :: "l"(dst), "f"(v.x * ne), "f"(v.y * ne), "f"(v.z * ne), "f"(v.w * ne)
                     : "memory");
        return;
    }

    // self-loop blocks
    int idx = (b - nbEdge) * blockDim.x + t;   // float4 index over [N*16)
    int row = idx >> 4;
    if (row >= N) return;
    int c4 = idx & 15;
    float invd = 1.0f / g_deg[row];            // broadcast across 16 threads
    float4 v = *reinterpret_cast<const float4*>(&g_xp[(size_t)row * OUT_F + c4 * 4]);
    float4 bb = reinterpret_cast<const float4*>(bias)[c4];
    float* dst = &out[(size_t)row * OUT_F + c4 * 4];
    asm volatile("red.global.add.v4.f32 [%0], {%1, %2, %3, %4};"
                 :: "l"(dst), "f"(fmaf(v.x, invd, bb.x)), "f"(fmaf(v.y, invd, bb.y)),
                    "f"(fmaf(v.z, invd, bb.z)), "f"(fmaf(v.w, invd, bb.w))
                 : "memory");
}

// ---------------------------------------------------------------------------
// Launch (3 launches)
// ---------------------------------------------------------------------------
extern "C" void kernel_launch(void* const* d_in, const int* in_sizes, int n_in,
                              void* d_out, int out_size) {
    const float* x    = (const float*)d_in[0];
    const void*  ei   = d_in[1];
    const float* W    = (const float*)d_in[2];
    const float* bias = (const float*)d_in[3];
    const float* ew   = (const float*)d_in[4];
    const float* u    = (const float*)d_in[5];
    float*       out  = (float*)d_out;

    int N = in_sizes[0] / IN_F;
    int E = in_sizes[4];
    if (N > NMAX) N = NMAX;
    if (E > EMAX) E = EMAX;

    int nbDegInit = (N + 255) / 256;
    // Each zero block covers 256 threads * 4 float4 = 1024 float4.
    int nbZero    = ((out_size >> 2) + 1023) / 1024;
    k_prep<<<2 + nbDegInit + nbZero, 256>>>((const unsigned int*)ei, 2 * E, W, u,
                                            out, out_size, N, nbDegInit);

    int nbDeg  = ((E + 3) / 4 + 255) / 256;
    int nbGemm = (N + 127) / 128;
    k_fused<<<nbDeg + nbGemm, 256>>>(x, ei, ew, N, E, nbDeg);

    int nbEdge = (E * 16 + 255) / 256;
    int nbSelf = (N * 16 + 255) / 256;
    k_scatter<<<nbEdge + nbSelf, 256>>>(bias, out, N, E, nbEdge);
}

// round 14
// speedup vs baseline: 2.1104x; 1.0307x over previous
#include <cuda_runtime.h>
#include <math.h>
#include <stdint.h>

#define NMAX 100000
#define EMAX 600000
#define IN_F 128
#define OUT_F 64

// Scratch (static device globals — allocation-free per harness rules)
__device__ float g_Wsn[IN_F * OUT_F];
__device__ float g_xp[(size_t)NMAX * OUT_F];
__device__ float g_deg[NMAX];
__device__ float g_w[EMAX];
__device__ int2  g_rc[EMAX];
__device__ int   g_is64;

__device__ __forceinline__ long long load_idx(const void* ei, size_t pos, int is64) {
    if (is64) return ((const long long*)ei)[pos];
    return (long long)(((const int*)ei)[pos]);
}

// ---------------------------------------------------------------------------
// 1) k_prep (block-switched, all paths independent):
//    b0: dtype detect | b1: spectral norm -> g_Wsn | deg=1 init | out=0 init
// ---------------------------------------------------------------------------
__global__ void k_prep(const unsigned int* __restrict__ ei_u32, int nwords,
                       const float* __restrict__ W, const float* __restrict__ u,
                       float* __restrict__ out, int out_size,
                       int N, int nbDeg) {
    int t = threadIdx.x;
    int b = blockIdx.x;

    if (b == 0) {
        __shared__ int any;
        if (t == 0) any = 0;
        __syncthreads();
        int limit = nwords < 8192 ? nwords : 8192;
        for (int i = 1 + 2 * t; i < limit; i += 2 * blockDim.x)
            if (ei_u32[i] != 0u) any = 1;
        __syncthreads();
        if (t == 0) g_is64 = (any == 0) ? 1 : 0;
        return;
    }
    if (b == 1) {
        // Spectral norm, fully coalesced.
        __shared__ float su[IN_F];
        __shared__ float sv[OUT_F];
        __shared__ float red1[4][OUT_F];   // matvec1 partials
        __shared__ float red16[16];        // matvec2 half-warp sq partials
        __shared__ float rsum[8];
        __shared__ float s_tn, s_inv;

        if (t < IN_F) su[t] = u[t];
        __syncthreads();

        // Matvec1: tj[j] = sum_i W[i*64+j] * u[i]; thread (j = t&63, quarter = t>>6)
        {
            int j = t & 63;
            int q = t >> 6;                // 0..3, i-range [q*32, q*32+32)
            float p = 0.f;
            int i0 = q * 32;
            #pragma unroll 8
            for (int i = 0; i < 32; i++) p += W[(i0 + i) * OUT_F + j] * su[i0 + i];
            red1[q][j] = p;
        }
        __syncthreads();

        // tj + norm^2 reduction (threads 0..63)
        float tj = 0.f;
        if (t < OUT_F) {
            tj = red1[0][t] + red1[1][t] + red1[2][t] + red1[3][t];
            float sq = tj * tj;
            #pragma unroll
            for (int o = 16; o > 0; o >>= 1) sq += __shfl_down_sync(0xffffffffu, sq, o);
            if ((t & 31) == 0) rsum[t >> 5] = sq;
        }
        __syncthreads();
        if (t == 0) s_tn = sqrtf(rsum[0] + rsum[1]) + 1e-12f;
        __syncthreads();
        if (t < OUT_F) sv[t] = tj / s_tn;
        __syncthreads();

        // Matvec2 (coalesced): half-warp per row; 16 half-warps x 8 passes.
        // Lane k of half-warp hw loads W[r*64 + k + 16m] (16 consecutive floats
        // per half-warp access). wv[r] reduced via width-16 shfl; only wv^2 kept.
        {
            int hw = t >> 4;
            int k = t & 15;
            float sq = 0.f;
            #pragma unroll
            for (int p = 0; p < 8; p++) {
                int r = p * 16 + hw;
                const float* wr = &W[r * OUT_F];
                float partial = wr[k]      * sv[k]
                              + wr[k + 16] * sv[k + 16]
                              + wr[k + 32] * sv[k + 32]
                              + wr[k + 48] * sv[k + 48];
                #pragma unroll
                for (int o = 8; o > 0; o >>= 1)
                    partial += __shfl_down_sync(0xffffffffu, partial, o, 16);
                if (k == 0) sq += partial * partial;
            }
            if (k == 0) red16[hw] = sq;
        }
        __syncthreads();
        if (t == 0) {
            float s2 = 0.f;
            #pragma unroll
            for (int i = 0; i < 16; i++) s2 += red16[i];
            float sigma = s2 / (sqrtf(s2) + 1e-12f);
            s_inv = 1.0f / sigma;
        }
        __syncthreads();

        // Scale W -> g_Wsn (coalesced float4)
        {
            float inv = s_inv;
            const float4* W4 = reinterpret_cast<const float4*>(W);
            float4* O4 = reinterpret_cast<float4*>(g_Wsn);
            #pragma unroll
            for (int i = 0; i < 8; i++) {
                int idx = t + i * 256;     // 2048 float4
                float4 v = W4[idx];
                O4[idx] = make_float4(v.x * inv, v.y * inv, v.z * inv, v.w * inv);
            }
        }
        return;
    }
    if (b < 2 + nbDeg) {
        int i = (b - 2) * blockDim.x + t;
        if (i < N) g_deg[i] = 1.0f;
        return;
    }
    // zero out: 4 float4 per thread => each block covers 1024 float4
    int base = ((b - 2 - nbDeg) * blockDim.x + t) * 4;
    int n4 = out_size >> 2;
    float4* o4 = reinterpret_cast<float4*>(out);
    #pragma unroll
    for (int i = 0; i < 4; i++) {
        int idx = base + i;
        if (idx < n4) o4[idx] = make_float4(0.f, 0.f, 0.f, 0.f);
    }
}

// ---------------------------------------------------------------------------
// 2) k_fused: deg-atomic blocks (memory-bound) overlap GEMM blocks (FMA-bound)
// ---------------------------------------------------------------------------
#define BK 32
#define XS_STRIDE 132
#define WS_STRIDE 17

__global__ void __launch_bounds__(256) k_fused(const float* __restrict__ x,
                                               const void* __restrict__ ei,
                                               const float* __restrict__ ew,
                                               int N, int E, int nbDeg) {
    int t = threadIdx.x;
    int b = blockIdx.x;

    if (b < nbDeg) {
        // ---- deg path ----
        int e = (b * blockDim.x + t) * 4;
        if (e >= E) return;
        int is64 = g_is64;
        if (e + 3 < E) {
            float4 w4 = *reinterpret_cast<const float4*>(ew + e);
            float4 s;
            s.x = 1.0f / (1.0f + expf(-w4.x));
            s.y = 1.0f / (1.0f + expf(-w4.y));
            s.z = 1.0f / (1.0f + expf(-w4.z));
            s.w = 1.0f / (1.0f + expf(-w4.w));
            *reinterpret_cast<float4*>(g_w + e) = s;
            int r0, r1, r2, r3, c0, c1, c2, c3;
            if (is64) {
                const longlong2* pr = reinterpret_cast<const longlong2*>((const long long*)ei + e);
                longlong2 a = pr[0], bq = pr[1];
                r0 = (int)a.x; r1 = (int)a.y; r2 = (int)bq.x; r3 = (int)bq.y;
                const longlong2* pc = reinterpret_cast<const longlong2*>((const long long*)ei + E + e);
                longlong2 d = pc[0], f = pc[1];
                c0 = (int)d.x; c1 = (int)d.y; c2 = (int)f.x; c3 = (int)f.y;
            } else {
                int4 rr = *reinterpret_cast<const int4*>((const int*)ei + e);
                r0 = rr.x; r1 = rr.y; r2 = rr.z; r3 = rr.w;
                int4 cc = *reinterpret_cast<const int4*>((const int*)ei + E + e);
                c0 = cc.x; c1 = cc.y; c2 = cc.z; c3 = cc.w;
            }
            int4* rcp = reinterpret_cast<int4*>(&g_rc[e]);
            rcp[0] = make_int4(r0, c0, r1, c1);
            rcp[1] = make_int4(r2, c2, r3, c3);
            atomicAdd(&g_deg[c0], s.x);
            atomicAdd(&g_deg[c1], s.y);
            atomicAdd(&g_deg[c2], s.z);
            atomicAdd(&g_deg[c3], s.w);
        } else {
            for (int k = e; k < E; k++) {
                float w = 1.0f / (1.0f + expf(-ew[k]));
                g_w[k] = w;
                int r = (int)load_idx(ei, (size_t)k, is64);
                int c = (int)load_idx(ei, (size_t)E + k, is64);
                g_rc[k] = make_int2(r, c);
                atomicAdd(&g_deg[c], w);
            }
        }
        return;
    }

    // ---- gemm path ----
    __shared__ float  xs[BK * XS_STRIDE];
    __shared__ float4 ws[BK * WS_STRIDE];

    int gb = b - nbDeg;
    int tx = t & 15;
    int ty = t >> 4;
    int row0 = gb * 128;

    float4 acc[8];
    #pragma unroll
    for (int r = 0; r < 8; r++) acc[r] = make_float4(0.f, 0.f, 0.f, 0.f);

    const float4* Wg = reinterpret_cast<const float4*>(g_Wsn);

    for (int kc = 0; kc < IN_F; kc += BK) {
        #pragma unroll
        for (int i = 0; i < 2; i++) {
            int idx = t + i * 256;
            int kk = idx >> 4;
            int c4 = idx & 15;
            ws[kk * WS_STRIDE + c4] = Wg[(kc + kk) * 16 + c4];
        }
        #pragma unroll
        for (int i = 0; i < 4; i++) {
            int idx = t + i * 256;
            int r = idx >> 3;
            int k4 = (idx & 7) << 2;
            float4 v = make_float4(0.f, 0.f, 0.f, 0.f);
            if (row0 + r < N)
                v = *reinterpret_cast<const float4*>(&x[(size_t)(row0 + r) * IN_F + kc + k4]);
            xs[(k4 + 0) * XS_STRIDE + r] = v.x;
            xs[(k4 + 1) * XS_STRIDE + r] = v.y;
            xs[(k4 + 2) * XS_STRIDE + r] = v.z;
            xs[(k4 + 3) * XS_STRIDE + r] = v.w;
        }
        __syncthreads();

        #pragma unroll 8
        for (int kk = 0; kk < BK; kk++) {
            float4 a0 = *reinterpret_cast<const float4*>(&xs[kk * XS_STRIDE + ty * 8]);
            float4 a1 = *reinterpret_cast<const float4*>(&xs[kk * XS_STRIDE + ty * 8 + 4]);
            float4 bb = ws[kk * WS_STRIDE + tx];
            acc[0].x += a0.x * bb.x; acc[0].y += a0.x * bb.y; acc[0].z += a0.x * bb.z; acc[0].w += a0.x * bb.w;
            acc[1].x += a0.y * bb.x; acc[1].y += a0.y * bb.y; acc[1].z += a0.y * bb.z; acc[1].w += a0.y * bb.w;
            acc[2].x += a0.z * bb.x; acc[2].y += a0.z * bb.y; acc[2].z += a0.z * bb.z; acc[2].w += a0.z * bb.w;
            acc[3].x += a0.w * bb.x; acc[3].y += a0.w * bb.y; acc[3].z += a0.w * bb.z; acc[3].w += a0.w * bb.w;
            acc[4].x += a1.x * bb.x; acc[4].y += a1.x * bb.y; acc[4].z += a1.x * bb.z; acc[4].w += a1.x * bb.w;
            acc[5].x += a1.y * bb.x; acc[5].y += a1.y * bb.y; acc[5].z += a1.y * bb.z; acc[5].w += a1.y * bb.w;
            acc[6].x += a1.z * bb.x; acc[6].y += a1.z * bb.y; acc[6].z += a1.z * bb.z; acc[6].w += a1.z * bb.w;
            acc[7].x += a1.w * bb.x; acc[7].y += a1.w * bb.y; acc[7].z += a1.w * bb.z; acc[7].w += a1.w * bb.w;
        }
        __syncthreads();
    }

    #pragma unroll
    for (int r = 0; r < 8; r++) {
        int row = row0 + ty * 8 + r;
        if (row >= N) break;
        *reinterpret_cast<float4*>(&g_xp[(size_t)row * OUT_F + tx * 4]) = acc[r];
    }
}

// ---------------------------------------------------------------------------
// 3) k_scatter (block-switched):
//    edge blocks: out[col] += xp[row] * (rsqrt(deg_r)*w*rsqrt(deg_c)), 16 lanes/edge
//    self blocks: out[row]  += xp[row]/deg + bias   (RED into zeroed out)
// ---------------------------------------------------------------------------
__global__ void k_scatter(const float* __restrict__ bias, float* __restrict__ out,
                          int N, int E, int nbEdge) {
    int t = threadIdx.x;
    int b = blockIdx.x;

    if (b < nbEdge) {
        int gid = b * blockDim.x + t;
        int e = gid >> 4;
        if (e >= E) return;
        int lane = gid & 15;

        int2 rc = g_rc[e];                                       // broadcast
        float ne = g_w[e] * rsqrtf(g_deg[rc.x]) * rsqrtf(g_deg[rc.y]);

        float4 v = *reinterpret_cast<const float4*>(&g_xp[(size_t)rc.x * OUT_F + lane * 4]);
        float* dst = &out[(size_t)rc.y * OUT_F + lane * 4];
        asm volatile("red.global.add.v4.f32 [%0], {%1, %2, %3, %4};"
                     :: "l"(dst), "f"(v.x * ne), "f"(v.y * ne), "f"(v.z * ne), "f"(v.w * ne)
                     : "memory");
        return;
    }

    // self-loop blocks
    int idx = (b - nbEdge) * blockDim.x + t;   // float4 index over [N*16)
    int row = idx >> 4;
    if (row >= N) return;
    int c4 = idx & 15;
    float invd = 1.0f / g_deg[row];            // broadcast across 16 threads
    float4 v = *reinterpret_cast<const float4*>(&g_xp[(size_t)row * OUT_F + c4 * 4]);
    float4 bb = reinterpret_cast<const float4*>(bias)[c4];
    float* dst = &out[(size_t)row * OUT_F + c4 * 4];
    asm volatile("red.global.add.v4.f32 [%0], {%1, %2, %3, %4};"
                 :: "l"(dst), "f"(fmaf(v.x, invd, bb.x)), "f"(fmaf(v.y, invd, bb.y)),
                    "f"(fmaf(v.z, invd, bb.z)), "f"(fmaf(v.w, invd, bb.w))
                 : "memory");
}

// ---------------------------------------------------------------------------
// Launch (3 launches)
// ---------------------------------------------------------------------------
extern "C" void kernel_launch(void* const* d_in, const int* in_sizes, int n_in,
                              void* d_out, int out_size) {
    const float* x    = (const float*)d_in[0];
    const void*  ei   = d_in[1];
    const float* W    = (const float*)d_in[2];
    const float* bias = (const float*)d_in[3];
    const float* ew   = (const float*)d_in[4];
    const float* u    = (const float*)d_in[5];
    float*       out  = (float*)d_out;

    int N = in_sizes[0] / IN_F;
    int E = in_sizes[4];
    if (N > NMAX) N = NMAX;
    if (E > EMAX) E = EMAX;

    int nbDegInit = (N + 255) / 256;
    // Each zero block covers 256 threads * 4 float4 = 1024 float4.
    int nbZero    = ((out_size >> 2) + 1023) / 1024;
    k_prep<<<2 + nbDegInit + nbZero, 256>>>((const unsigned int*)ei, 2 * E, W, u,
                                            out, out_size, N, nbDegInit);

    int nbDeg  = ((E + 3) / 4 + 255) / 256;
    int nbGemm = (N + 127) / 128;
    k_fused<<<nbDeg + nbGemm, 256>>>(x, ei, ew, N, E, nbDeg);

    int nbEdge = (E * 16 + 255) / 256;
    int nbSelf = (N * 16 + 255) / 256;
    k_scatter<<<nbEdge + nbSelf, 256>>>(bias, out, N, E, nbEdge);
}

// round 15
// speedup vs baseline: 2.1671x; 1.0269x over previous
#include <cuda_runtime.h>
#include <math.h>
#include <stdint.h>

#define NMAX 100000
#define EMAX 600000
#define IN_F 128
#define OUT_F 64

// Scratch (static device globals — allocation-free per harness rules)
__device__ float g_Wsn[IN_F * OUT_F];
__device__ float g_xp[(size_t)NMAX * OUT_F];
__device__ float g_deg[NMAX];
__device__ float g_w[EMAX];
__device__ int2  g_rc[EMAX];
__device__ int   g_is64;

__device__ __forceinline__ long long load_idx(const void* ei, size_t pos, int is64) {
    if (is64) return ((const long long*)ei)[pos];
    return (long long)(((const int*)ei)[pos]);
}

// ---------------------------------------------------------------------------
// 1) k_prep (block-switched):
//    b0: dtype detect | b1: spectral norm -> g_Wsn | rest: deg=1 init
//    (out zero-pass removed — self-loop kernel now plain-stores out)
// ---------------------------------------------------------------------------
__global__ void k_prep(const unsigned int* __restrict__ ei_u32, int nwords,
                       const float* __restrict__ W, const float* __restrict__ u,
                       int N) {
    int t = threadIdx.x;
    int b = blockIdx.x;

    if (b == 0) {
        __shared__ int any;
        if (t == 0) any = 0;
        __syncthreads();
        int limit = nwords < 8192 ? nwords : 8192;
        for (int i = 1 + 2 * t; i < limit; i += 2 * blockDim.x)
            if (ei_u32[i] != 0u) any = 1;
        __syncthreads();
        if (t == 0) g_is64 = (any == 0) ? 1 : 0;
        return;
    }
    if (b == 1) {
        // Spectral norm, fully coalesced.
        __shared__ float su[IN_F];
        __shared__ float sv[OUT_F];
        __shared__ float red1[4][OUT_F];
        __shared__ float red16[16];
        __shared__ float rsum[8];
        __shared__ float s_tn, s_inv;

        if (t < IN_F) su[t] = u[t];
        __syncthreads();

        // Matvec1: tj[j] = sum_i W[i*64+j] * u[i]
        {
            int j = t & 63;
            int q = t >> 6;
            float p = 0.f;
            int i0 = q * 32;
            #pragma unroll 8
            for (int i = 0; i < 32; i++) p += W[(i0 + i) * OUT_F + j] * su[i0 + i];
            red1[q][j] = p;
        }
        __syncthreads();

        float tj = 0.f;
        if (t < OUT_F) {
            tj = red1[0][t] + red1[1][t] + red1[2][t] + red1[3][t];
            float sq = tj * tj;
            #pragma unroll
            for (int o = 16; o > 0; o >>= 1) sq += __shfl_down_sync(0xffffffffu, sq, o);
            if ((t & 31) == 0) rsum[t >> 5] = sq;
        }
        __syncthreads();
        if (t == 0) s_tn = sqrtf(rsum[0] + rsum[1]) + 1e-12f;
        __syncthreads();
        if (t < OUT_F) sv[t] = tj / s_tn;
        __syncthreads();

        // Matvec2 (coalesced): half-warp per row
        {
            int hw = t >> 4;
            int k = t & 15;
            float sq = 0.f;
            #pragma unroll
            for (int p = 0; p < 8; p++) {
                int r = p * 16 + hw;
                const float* wr = &W[r * OUT_F];
                float partial = wr[k]      * sv[k]
                              + wr[k + 16] * sv[k + 16]
                              + wr[k + 32] * sv[k + 32]
                              + wr[k + 48] * sv[k + 48];
                #pragma unroll
                for (int o = 8; o > 0; o >>= 1)
                    partial += __shfl_down_sync(0xffffffffu, partial, o, 16);
                if (k == 0) sq += partial * partial;
            }
            if (k == 0) red16[hw] = sq;
        }
        __syncthreads();
        if (t == 0) {
            float s2 = 0.f;
            #pragma unroll
            for (int i = 0; i < 16; i++) s2 += red16[i];
            float sigma = s2 / (sqrtf(s2) + 1e-12f);
            s_inv = 1.0f / sigma;
        }
        __syncthreads();

        {
            float inv = s_inv;
            const float4* W4 = reinterpret_cast<const float4*>(W);
            float4* O4 = reinterpret_cast<float4*>(g_Wsn);
            #pragma unroll
            for (int i = 0; i < 8; i++) {
                int idx = t + i * 256;
                float4 v = W4[idx];
                O4[idx] = make_float4(v.x * inv, v.y * inv, v.z * inv, v.w * inv);
            }
        }
        return;
    }
    int i = (b - 2) * blockDim.x + t;
    if (i < N) g_deg[i] = 1.0f;
}

// ---------------------------------------------------------------------------
// 2) k_fused: deg-atomic blocks (memory-bound) overlap GEMM blocks (FMA-bound)
// ---------------------------------------------------------------------------
#define BK 32
#define XS_STRIDE 132
#define WS_STRIDE 17

__global__ void __launch_bounds__(256) k_fused(const float* __restrict__ x,
                                               const void* __restrict__ ei,
                                               const float* __restrict__ ew,
                                               int N, int E, int nbDeg) {
    int t = threadIdx.x;
    int b = blockIdx.x;

    if (b < nbDeg) {
        // ---- deg path ----
        int e = (b * blockDim.x + t) * 4;
        if (e >= E) return;
        int is64 = g_is64;
        if (e + 3 < E) {
            float4 w4 = *reinterpret_cast<const float4*>(ew + e);
            float4 s;
            s.x = 1.0f / (1.0f + expf(-w4.x));
            s.y = 1.0f / (1.0f + expf(-w4.y));
            s.z = 1.0f / (1.0f + expf(-w4.z));
            s.w = 1.0f / (1.0f + expf(-w4.w));
            *reinterpret_cast<float4*>(g_w + e) = s;
            int r0, r1, r2, r3, c0, c1, c2, c3;
            if (is64) {
                const longlong2* pr = reinterpret_cast<const longlong2*>((const long long*)ei + e);
                longlong2 a = pr[0], bq = pr[1];
                r0 = (int)a.x; r1 = (int)a.y; r2 = (int)bq.x; r3 = (int)bq.y;
                const longlong2* pc = reinterpret_cast<const longlong2*>((const long long*)ei + E + e);
                longlong2 d = pc[0], f = pc[1];
                c0 = (int)d.x; c1 = (int)d.y; c2 = (int)f.x; c3 = (int)f.y;
            } else {
                int4 rr = *reinterpret_cast<const int4*>((const int*)ei + e);
                r0 = rr.x; r1 = rr.y; r2 = rr.z; r3 = rr.w;
                int4 cc = *reinterpret_cast<const int4*>((const int*)ei + E + e);
                c0 = cc.x; c1 = cc.y; c2 = cc.z; c3 = cc.w;
            }
            int4* rcp = reinterpret_cast<int4*>(&g_rc[e]);
            rcp[0] = make_int4(r0, c0, r1, c1);
            rcp[1] = make_int4(r2, c2, r3, c3);
            atomicAdd(&g_deg[c0], s.x);
            atomicAdd(&g_deg[c1], s.y);
            atomicAdd(&g_deg[c2], s.z);
            atomicAdd(&g_deg[c3], s.w);
        } else {
            for (int k = e; k < E; k++) {
                float w = 1.0f / (1.0f + expf(-ew[k]));
                g_w[k] = w;
                int r = (int)load_idx(ei, (size_t)k, is64);
                int c = (int)load_idx(ei, (size_t)E + k, is64);
                g_rc[k] = make_int2(r, c);
                atomicAdd(&g_deg[c], w);
            }
        }
        return;
    }

    // ---- gemm path ----
    __shared__ float  xs[BK * XS_STRIDE];
    __shared__ float4 ws[BK * WS_STRIDE];

    int gb = b - nbDeg;
    int tx = t & 15;
    int ty = t >> 4;
    int row0 = gb * 128;

    float4 acc[8];
    #pragma unroll
    for (int r = 0; r < 8; r++) acc[r] = make_float4(0.f, 0.f, 0.f, 0.f);

    const float4* Wg = reinterpret_cast<const float4*>(g_Wsn);

    for (int kc = 0; kc < IN_F; kc += BK) {
        #pragma unroll
        for (int i = 0; i < 2; i++) {
            int idx = t + i * 256;
            int kk = idx >> 4;
            int c4 = idx & 15;
            ws[kk * WS_STRIDE + c4] = Wg[(kc + kk) * 16 + c4];
        }
        #pragma unroll
        for (int i = 0; i < 4; i++) {
            int idx = t + i * 256;
            int r = idx >> 3;
            int k4 = (idx & 7) << 2;
            float4 v = make_float4(0.f, 0.f, 0.f, 0.f);
            if (row0 + r < N)
                v = *reinterpret_cast<const float4*>(&x[(size_t)(row0 + r) * IN_F + kc + k4]);
            xs[(k4 + 0) * XS_STRIDE + r] = v.x;
            xs[(k4 + 1) * XS_STRIDE + r] = v.y;
            xs[(k4 + 2) * XS_STRIDE + r] = v.z;
            xs[(k4 + 3) * XS_STRIDE + r] = v.w;
        }
        __syncthreads();

        #pragma unroll 8
        for (int kk = 0; kk < BK; kk++) {
            float4 a0 = *reinterpret_cast<const float4*>(&xs[kk * XS_STRIDE + ty * 8]);
            float4 a1 = *reinterpret_cast<const float4*>(&xs[kk * XS_STRIDE + ty * 8 + 4]);
            float4 bb = ws[kk * WS_STRIDE + tx];
            acc[0].x += a0.x * bb.x; acc[0].y += a0.x * bb.y; acc[0].z += a0.x * bb.z; acc[0].w += a0.x * bb.w;
            acc[1].x += a0.y * bb.x; acc[1].y += a0.y * bb.y; acc[1].z += a0.y * bb.z; acc[1].w += a0.y * bb.w;
            acc[2].x += a0.z * bb.x; acc[2].y += a0.z * bb.y; acc[2].z += a0.z * bb.z; acc[2].w += a0.z * bb.w;
            acc[3].x += a0.w * bb.x; acc[3].y += a0.w * bb.y; acc[3].z += a0.w * bb.z; acc[3].w += a0.w * bb.w;
            acc[4].x += a1.x * bb.x; acc[4].y += a1.x * bb.y; acc[4].z += a1.x * bb.z; acc[4].w += a1.x * bb.w;
            acc[5].x += a1.y * bb.x; acc[5].y += a1.y * bb.y; acc[5].z += a1.y * bb.z; acc[5].w += a1.y * bb.w;
            acc[6].x += a1.z * bb.x; acc[6].y += a1.z * bb.y; acc[6].z += a1.z * bb.z; acc[6].w += a1.z * bb.w;
            acc[7].x += a1.w * bb.x; acc[7].y += a1.w * bb.y; acc[7].z += a1.w * bb.z; acc[7].w += a1.w * bb.w;
        }
        __syncthreads();
    }

    #pragma unroll
    for (int r = 0; r < 8; r++) {
        int row = row0 + ty * 8 + r;
        if (row >= N) break;
        *reinterpret_cast<float4*>(&g_xp[(size_t)row * OUT_F + tx * 4]) = acc[r];
    }
}

// ---------------------------------------------------------------------------
// 3) k_self: out = xp/deg + bias  (plain float4 stores — no zeroing needed)
// ---------------------------------------------------------------------------
__global__ void k_self(const float* __restrict__ bias, float* __restrict__ out, int N) {
    int idx = blockIdx.x * blockDim.x + threadIdx.x;   // float4 index over [N*16)
    int row = idx >> 4;
    if (row >= N) return;
    int c4 = idx & 15;
    float invd = 1.0f / g_deg[row];                    // broadcast across 16 threads
    float4 v = *reinterpret_cast<const float4*>(&g_xp[(size_t)row * OUT_F + c4 * 4]);
    float4 bb = reinterpret_cast<const float4*>(bias)[c4];
    *reinterpret_cast<float4*>(&out[(size_t)row * OUT_F + c4 * 4]) =
        make_float4(fmaf(v.x, invd, bb.x), fmaf(v.y, invd, bb.y),
                    fmaf(v.z, invd, bb.z), fmaf(v.w, invd, bb.w));
}

// ---------------------------------------------------------------------------
// 4) k_scatter: edges only — out[col] += xp[row] * (rsqrt*w*rsqrt), 16 lanes/edge
// ---------------------------------------------------------------------------
__global__ void k_scatter(float* __restrict__ out, int E) {
    int gid = blockIdx.x * blockDim.x + threadIdx.x;
    int e = gid >> 4;
    if (e >= E) return;
    int lane = gid & 15;

    int2 rc = g_rc[e];                                       // broadcast
    float ne = g_w[e] * rsqrtf(g_deg[rc.x]) * rsqrtf(g_deg[rc.y]);

    float4 v = *reinterpret_cast<const float4*>(&g_xp[(size_t)rc.x * OUT_F + lane * 4]);
    float* dst = &out[(size_t)rc.y * OUT_F + lane * 4];
    asm volatile("red.global.add.v4.f32 [%0], {%1, %2, %3, %4};"
                 :: "l"(dst), "f"(v.x * ne), "f"(v.y * ne), "f"(v.z * ne), "f"(v.w * ne)
                 : "memory");
}

// ---------------------------------------------------------------------------
// Launch (4 launches; stream order guarantees self-stores precede edge-REDs)
// ---------------------------------------------------------------------------
extern "C" void kernel_launch(void* const* d_in, const int* in_sizes, int n_in,
                              void* d_out, int out_size) {
    const float* x    = (const float*)d_in[0];
    const void*  ei   = d_in[1];
    const float* W    = (const float*)d_in[2];
    const float* bias = (const float*)d_in[3];
    const float* ew   = (const float*)d_in[4];
    const float* u    = (const float*)d_in[5];
    float*       out  = (float*)d_out;

    int N = in_sizes[0] / IN_F;
    int E = in_sizes[4];
    if (N > NMAX) N = NMAX;
    if (E > EMAX) E = EMAX;

    int nbDegInit = (N + 255) / 256;
    k_prep<<<2 + nbDegInit, 256>>>((const unsigned int*)ei, 2 * E, W, u, N);

    int nbDeg  = ((E + 3) / 4 + 255) / 256;
    int nbGemm = (N + 127) / 128;
    k_fused<<<nbDeg + nbGemm, 256>>>(x, ei, ew, N, E, nbDeg);

    k_self<<<(N * 16 + 255) / 256, 256>>>(bias, out, N);

    k_scatter<<<(E * 16 + 255) / 256, 256>>>(out, E);
}